// round 14
// baseline (speedup 1.0000x reference)
#include <cuda_runtime.h>
#include <cuda_bf16.h>
#include <math.h>
#include <stdint.h>

// Problem dims
#define BB   512
#define XDIM 32768
#define PDIM 512
#define DDIM 64
#define HDIM 128
#define G1D  1024

// Shared HMMA config
#define BM 128
#define BK 32
#define PITCH 40
#define ROWB (PITCH * 2)        // 80

// gemm_bs (BN=128)
#define MAT_BYTES (128 * ROWB)        // 10240
#define STG_BYTES (4 * MAT_BYTES)     // 40960
#define GEMM_SMEM (2 * STG_BYTES)     // 81920

// K1 (BM=128, BN=256, KS=8, 3-stage, 256 threads) — R9 config
#define K1_BN 256
#define K1_KS 8
#define K1_KCHUNK (XDIM / K1_KS)      // 4096
#define K1_NIT (K1_KCHUNK / BK)       // 128
#define K1_MAT_A 10240                // 128 rows x 80B
#define K1_B_PITCH 528                // 256 n x 2B + 16B pad
#define K1_MAT_B (32 * K1_B_PITCH)    // 16896
#define K1_AH 0
#define K1_AL K1_MAT_A
#define K1_BH (2 * K1_MAT_A)
#define K1_BL (2 * K1_MAT_A + K1_MAT_B)
#define K1_STG (2 * K1_MAT_A + 2 * K1_MAT_B)   // 54272
#define K1_SMEM (3 * K1_STG)                   // 162816

// conv tile counts (piggybacked on K1's idle SMs)
#define NT_WG2 512                   // 16 x 32
#define NT_WH  4096                  // 4 x 16 x 64
#define NT_W2  1024                  // 4 x 4 x 64
#define NT_ALL (NT_WG2 + NT_WH + NT_W2)   // 5632
#define CONV_BLOCKS 16

// ---------------- device scratch ----------------
__device__ float g_part[K1_KS * BB * G1D];     // 16 MB
__device__ __nv_bfloat16 g_h1hi[BB * G1D];
__device__ __nv_bfloat16 g_h1lo[BB * G1D];
__device__ __nv_bfloat16 g_wg2thi[PDIM * G1D];
__device__ __nv_bfloat16 g_wg2tlo[PDIM * G1D];
__device__ __nv_bfloat16 g_hhi[BB * PDIM];
__device__ __nv_bfloat16 g_hlo[BB * PDIM];
__device__ __nv_bfloat16 g_whthi[DDIM * HDIM * PDIM];
__device__ __nv_bfloat16 g_whtlo[DDIM * HDIM * PDIM];
__device__ float g_hWh[DDIM * BB * HDIM];
__device__ __nv_bfloat16 g_w2thi[DDIM * HDIM * HDIM];
__device__ __nv_bfloat16 g_w2tlo[DDIM * HDIM * HDIM];
__device__ float g_js[DDIM * 8];
__device__ float g_es[DDIM * 8];

__device__ __forceinline__ float eluf(float x) {
    return x > 0.f ? x : expm1f(x);
}
__device__ __forceinline__ uint32_t smem_u32(const void* p) {
    uint32_t a;
    asm("{ .reg .u64 t; cvta.to.shared.u64 t, %1; cvt.u32.u64 %0, t; }"
        : "=r"(a) : "l"(p));
    return a;
}
#define CP16(dst, src) \
    asm volatile("cp.async.cg.shared.global [%0], [%1], 16;" \
                 :: "r"(dst), "l"(src) : "memory")
#define CP_COMMIT() asm volatile("cp.async.commit_group;" ::: "memory")
#define CP_WAIT1()  asm volatile("cp.async.wait_group 1;" ::: "memory")
#define CP_WAIT0()  asm volatile("cp.async.wait_group 0;" ::: "memory")

__device__ __forceinline__ void ldmx4(uint32_t* r, uint32_t addr) {
    asm volatile("ldmatrix.sync.aligned.m8n8.x4.shared.b16 {%0,%1,%2,%3}, [%4];"
                 : "=r"(r[0]), "=r"(r[1]), "=r"(r[2]), "=r"(r[3]) : "r"(addr));
}
__device__ __forceinline__ void ldmx4t(uint32_t* r, uint32_t addr) {
    asm volatile("ldmatrix.sync.aligned.m8n8.x4.trans.shared.b16 {%0,%1,%2,%3}, [%4];"
                 : "=r"(r[0]), "=r"(r[1]), "=r"(r[2]), "=r"(r[3]) : "r"(addr));
}
__device__ __forceinline__ void mma16816(float* c, const uint32_t* a,
                                         uint32_t b0, uint32_t b1) {
    asm volatile(
        "mma.sync.aligned.m16n8k16.row.col.f32.bf16.bf16.f32 "
        "{%0,%1,%2,%3}, {%4,%5,%6,%7}, {%8,%9}, {%0,%1,%2,%3};"
        : "+f"(c[0]), "+f"(c[1]), "+f"(c[2]), "+f"(c[3])
        : "r"(a[0]), "r"(a[1]), "r"(a[2]), "r"(a[3]), "r"(b0), "r"(b1));
}
__device__ __forceinline__ void hilo(float v, __nv_bfloat16& h, __nv_bfloat16& l) {
    h = __float2bfloat16(v);
    l = __float2bfloat16(v - __bfloat162float(h));
}
// pack 8 fp32 -> 16B hi + 16B lo
__device__ __forceinline__ void pack8(const float* v, uint4& H, uint4& L) {
    uint32_t hw[4], lw[4];
#pragma unroll
    for (int j = 0; j < 4; j++) {
        __nv_bfloat16 h0, l0, h1, l1;
        hilo(v[2 * j], h0, l0);
        hilo(v[2 * j + 1], h1, l1);
        __nv_bfloat162 ph; ph.x = h0; ph.y = h1;
        __nv_bfloat162 pl; pl.x = l0; pl.y = l1;
        hw[j] = *(uint32_t*)&ph;
        lw[j] = *(uint32_t*)&pl;
    }
    H = make_uint4(hw[0], hw[1], hw[2], hw[3]);
    L = make_uint4(lw[0], lw[1], lw[2], lw[3]);
}

// one 32x32 transpose-convert tile (256 threads), smem tile s[32*33]
__device__ void conv_tile(const float* __restrict__ src,
                          __nv_bfloat16* __restrict__ dhi,
                          __nv_bfloat16* __restrict__ dlo,
                          int R, int C, int zi, int rt, int ct,
                          float* s, int tid) {
    const size_t zoff = (size_t)zi * R * C;
    const int tx = tid & 31, ty = tid >> 5;   // 32 x 8
    for (int r = ty; r < 32; r += 8)
        s[r * 33 + tx] = src[zoff + (size_t)(rt * 32 + r) * C + ct * 32 + tx];
    __syncthreads();
    for (int c = ty; c < 32; c += 8) {
        float v = s[tx * 33 + c];
        __nv_bfloat16 h, l;
        hilo(v, h, l);
        dhi[zoff + (size_t)(ct * 32 + c) * R + rt * 32 + tx] = h;
        dlo[zoff + (size_t)(ct * 32 + c) * R + rt * 32 + tx] = l;
    }
    __syncthreads();
}

// ---------------- K1 (R9 exact) + piggybacked weight conversion -------------
__global__ void __launch_bounds__(256, 1) gemm_k1_kernel(
    const float* __restrict__ x, const float* __restrict__ Wg1,
    const float* __restrict__ Wg2, const float* __restrict__ Wh,
    const float* __restrict__ W2)
{
    extern __shared__ char sm[];
    const int tid = threadIdx.x;

    // conv blocks: blockIdx.z == K1_KS
    if (blockIdx.z == K1_KS) {
        float* s = (float*)sm;
        const int bid = blockIdx.x + 4 * blockIdx.y;   // 0..15
        for (int t = bid; t < NT_ALL; t += CONV_BLOCKS) {
            if (t < NT_WG2) {
                conv_tile(Wg2, g_wg2thi, g_wg2tlo, G1D, PDIM,
                          0, t / 16, t % 16, s, tid);
            } else if (t < NT_WG2 + NT_WH) {
                int u = t - NT_WG2;
                conv_tile(Wh, g_whthi, g_whtlo, PDIM, HDIM,
                          u / 64, (u % 64) / 4, (u % 64) % 4, s, tid);
            } else {
                int u = t - NT_WG2 - NT_WH;
                conv_tile(W2, g_w2thi, g_w2tlo, HDIM, HDIM,
                          u / 16, (u % 16) / 4, (u % 16) % 4, s, tid);
            }
        }
        return;
    }

    const uint32_t sb = smem_u32(sm);
    const int lane = tid & 31;
    const int wid = tid >> 5;
    const int warpM = wid >> 2;   // 0..1 -> 64 rows
    const int warpN = wid & 3;    // 0..3 -> 64 cols

    const int nBase = blockIdx.x * K1_BN;
    const int mBase = blockIdx.y * BM;
    const int kBase = blockIdx.z * K1_KCHUNK;

    const uint32_t laneOffA =
        (uint32_t)(((lane & 7) + ((lane >> 3) & 1) * 8) * ROWB + (lane >> 4) * 16);
    const uint32_t laneOffB =
        (uint32_t)(((lane & 7) + ((lane >> 3) & 1) * 8) * K1_B_PITCH +
                   (lane >> 4) * 16);

    float acc[4][8][4];
#pragma unroll
    for (int i = 0; i < 4; i++)
#pragma unroll
        for (int j = 0; j < 8; j++)
#pragma unroll
            for (int k = 0; k < 4; k++) acc[i][j][k] = 0.f;

    float pfA[2][8], pfB[4][8];

    auto LDG_STAGE = [&](int itn) {
        const int k0 = kBase + itn * BK;
#pragma unroll
        for (int t = 0; t < 2; t++) {
            int u = tid + t * 256;
            int m = u >> 2, kc = (u & 3) * 8;
            const float4* s = (const float4*)(x + (size_t)(mBase + m) * XDIM + k0 + kc);
            float4 v0 = __ldg(s), v1 = __ldg(s + 1);
            pfA[t][0] = v0.x; pfA[t][1] = v0.y; pfA[t][2] = v0.z; pfA[t][3] = v0.w;
            pfA[t][4] = v1.x; pfA[t][5] = v1.y; pfA[t][6] = v1.z; pfA[t][7] = v1.w;
        }
#pragma unroll
        for (int t = 0; t < 4; t++) {
            int u = tid + t * 256;
            int k = u >> 5, n8 = (u & 31) * 8;
            const float4* s = (const float4*)(Wg1 + (size_t)(k0 + k) * G1D + nBase + n8);
            float4 v0 = __ldg(s), v1 = __ldg(s + 1);
            pfB[t][0] = v0.x; pfB[t][1] = v0.y; pfB[t][2] = v0.z; pfB[t][3] = v0.w;
            pfB[t][4] = v1.x; pfB[t][5] = v1.y; pfB[t][6] = v1.z; pfB[t][7] = v1.w;
        }
    };
    auto STS_STAGE = [&](int stage) {
        char* st = sm + (size_t)stage * K1_STG;
#pragma unroll
        for (int t = 0; t < 2; t++) {
            int u = tid + t * 256;
            int m = u >> 2, kc = (u & 3) * 8;
            uint4 H, L;
            pack8(pfA[t], H, L);
            uint32_t so = (uint32_t)(m * ROWB + kc * 2);
            *(uint4*)(st + K1_AH + so) = H;
            *(uint4*)(st + K1_AL + so) = L;
        }
#pragma unroll
        for (int t = 0; t < 4; t++) {
            int u = tid + t * 256;
            int k = u >> 5, n8 = (u & 31) * 8;
            uint4 H, L;
            pack8(pfB[t], H, L);
            uint32_t so = (uint32_t)(k * K1_B_PITCH + n8 * 2);
            *(uint4*)(st + K1_BH + so) = H;
            *(uint4*)(st + K1_BL + so) = L;
        }
    };

    LDG_STAGE(0); STS_STAGE(0);
    LDG_STAGE(1); STS_STAGE(1);
    __syncthreads();

#pragma unroll 1
    for (int it = 0; it < K1_NIT; it++) {
        const bool pf = (it + 2 < K1_NIT);
        if (pf) LDG_STAGE(it + 2);

        uint32_t st = sb + (uint32_t)(it % 3) * K1_STG;
        uint32_t aH = st + K1_AH + (uint32_t)(warpM * 64) * ROWB + laneOffA;
        uint32_t aL = st + K1_AL + (uint32_t)(warpM * 64) * ROWB + laneOffA;
        uint32_t bH = st + K1_BH + (uint32_t)(warpN * 64) * 2 + laneOffB;
        uint32_t bL = st + K1_BL + (uint32_t)(warpN * 64) * 2 + laneOffB;

#pragma unroll
        for (int ks = 0; ks < 2; ks++) {
            const uint32_t kbA = ks * 32;
            const uint32_t kbB = ks * 16 * K1_B_PITCH;
            uint32_t ah[4][4], al[4][4];
#pragma unroll
            for (int mt = 0; mt < 4; mt++) {
                ldmx4(ah[mt], aH + (uint32_t)(mt * 16) * ROWB + kbA);
                ldmx4(al[mt], aL + (uint32_t)(mt * 16) * ROWB + kbA);
            }
#pragma unroll
            for (int p = 0; p < 4; p++) {
                uint32_t bh[4], bl[4];
                ldmx4t(bh, bH + (uint32_t)(p * 32) + kbB);
                ldmx4t(bl, bL + (uint32_t)(p * 32) + kbB);
#pragma unroll
                for (int mt = 0; mt < 4; mt++) {
                    mma16816(acc[mt][2 * p], ah[mt], bh[0], bh[1]);
                    mma16816(acc[mt][2 * p], ah[mt], bl[0], bl[1]);
                    mma16816(acc[mt][2 * p], al[mt], bh[0], bh[1]);
                    mma16816(acc[mt][2 * p + 1], ah[mt], bh[2], bh[3]);
                    mma16816(acc[mt][2 * p + 1], ah[mt], bl[2], bl[3]);
                    mma16816(acc[mt][2 * p + 1], al[mt], bh[2], bh[3]);
                }
            }
        }

        if (pf) STS_STAGE((it + 2) % 3);
        __syncthreads();
    }

    float* base = g_part + (size_t)blockIdx.z * (BB * G1D);
#pragma unroll
    for (int mt = 0; mt < 4; mt++) {
        int m0 = mBase + warpM * 64 + mt * 16 + (lane >> 2);
#pragma unroll
        for (int nt = 0; nt < 8; nt++) {
            int n0 = nBase + warpN * 64 + nt * 8 + (lane & 3) * 2;
            *(float2*)(base + (size_t)m0 * G1D + n0) =
                make_float2(acc[mt][nt][0], acc[mt][nt][1]);
            *(float2*)(base + (size_t)(m0 + 8) * G1D + n0) =
                make_float2(acc[mt][nt][2], acc[mt][nt][3]);
        }
    }
}

// partials -> h1 = elu(sum + bias), bf16 hi/lo (float4)
__global__ void reduce_h1_kernel(const float* __restrict__ bg1) {
    const int i4 = blockIdx.x * 256 + threadIdx.x;
    float4 s = make_float4(0.f, 0.f, 0.f, 0.f);
#pragma unroll
    for (int k = 0; k < K1_KS; k++) {
        float4 v = ((const float4*)g_part)[k * (BB * G1D / 4) + i4];
        s.x += v.x; s.y += v.y; s.z += v.z; s.w += v.w;
    }
    const int c0 = (i4 * 4) & (G1D - 1);
    float4 b = *(const float4*)(bg1 + c0);
    float u0 = eluf(s.x + b.x), u1 = eluf(s.y + b.y);
    float u2 = eluf(s.z + b.z), u3 = eluf(s.w + b.w);
    __nv_bfloat16 h0, h1, h2, h3, l0, l1, l2, l3;
    hilo(u0, h0, l0); hilo(u1, h1, l1); hilo(u2, h2, l2); hilo(u3, h3, l3);
    __nv_bfloat162 vh0, vh1, vl0, vl1;
    vh0.x = h0; vh0.y = h1; vh1.x = h2; vh1.y = h3;
    vl0.x = l0; vl0.y = l1; vl1.x = l2; vl1.y = l3;
    ((__nv_bfloat162*)g_h1hi)[2 * i4] = vh0;
    ((__nv_bfloat162*)g_h1hi)[2 * i4 + 1] = vh1;
    ((__nv_bfloat162*)g_h1lo)[2 * i4] = vl0;
    ((__nv_bfloat162*)g_h1lo)[2 * i4 + 1] = vl1;
}

// ---------------- unified bf16-split HMMA GEMM (BN=128) ----------------
template <int EPI>
__global__ void __launch_bounds__(256, 2) gemm_bs(
    const __nv_bfloat16* __restrict__ Ahi, const __nv_bfloat16* __restrict__ Alo,
    int lda, long sAz,
    const __nv_bfloat16* __restrict__ Bhi, const __nv_bfloat16* __restrict__ Blo,
    int ldb, long sBz,
    float* __restrict__ C, __nv_bfloat16* __restrict__ Chi,
    __nv_bfloat16* __restrict__ Clo,
    const float* __restrict__ bias, int ldc, long sCz, int K,
    const float* __restrict__ b2, const float* __restrict__ W3,
    const float* __restrict__ b3,
    const float* __restrict__ hwhp, const float* __restrict__ zv,
    const int* __restrict__ permp, const float* __restrict__ Wzp,
    const float* __restrict__ b1p)
{
    extern __shared__ char sm[];
    __shared__ float red[128][5];
    __shared__ float wr[8];
    __shared__ float s_wz[HDIM], s_b1[HDIM];
    const uint32_t sb = smem_u32(sm);
    const int tid = threadIdx.x;
    const int lane = tid & 31;
    const int wid = tid >> 5;
    const int warpM = wid >> 2;
    const int warpN = wid & 3;

    const int nBase = blockIdx.x * 128;
    const int mBase = blockIdx.y * BM;
    const __nv_bfloat16* ahiz = Ahi + (size_t)blockIdx.z * sAz;
    const __nv_bfloat16* aloz = Alo + (size_t)blockIdx.z * sAz;
    const __nv_bfloat16* bhi = Bhi + (size_t)blockIdx.z * sBz;
    const __nv_bfloat16* blo = Blo + (size_t)blockIdx.z * sBz;

    if (EPI == 2) {
        if (tid < HDIM) {
            s_wz[tid] = Wzp[(size_t)blockIdx.z * HDIM + tid];
            s_b1[tid] = b1p[(size_t)blockIdx.z * HDIM + tid];
        }
        __syncthreads();
    }

    const uint32_t laneOff =
        (uint32_t)(((lane & 7) + ((lane >> 3) & 1) * 8) * ROWB + (lane >> 4) * 16);
    const int NIT = K / BK;

    float acc[4][4][4];
#pragma unroll
    for (int i = 0; i < 4; i++)
#pragma unroll
        for (int j = 0; j < 4; j++)
#pragma unroll
            for (int k = 0; k < 4; k++) acc[i][j][k] = 0.f;

#define A_COMPUTE(stage, k0)                                                   \
    do {                                                                       \
        uint32_t stoff = (uint32_t)(stage) * STG_BYTES;                        \
        const float* hwh_d = hwhp + (size_t)blockIdx.z * BB * HDIM;            \
        _Pragma("unroll")                                                      \
        for (int t = 0; t < 2; t++) {                                          \
            int u = tid + t * 256;                                             \
            int r = u >> 2, ch = u & 3;                                        \
            int gm = mBase + r;                                                \
            int b = (gm < BB) ? gm : gm - BB;                                  \
            int src = (gm < BB) ? b : __ldg(permp + b);                        \
            float zb = __ldg(zv + (size_t)b * DDIM + blockIdx.z);              \
            const float* hr = hwh_d + (size_t)src * HDIM + (k0) + ch * 8;      \
            float4 v0 = __ldg((const float4*)hr);                              \
            float4 v1 = __ldg((const float4*)(hr + 4));                        \
            float hv[8] = {v0.x, v0.y, v0.z, v0.w, v1.x, v1.y, v1.z, v1.w};    \
            uint32_t hp[4], lp[4];                                             \
            _Pragma("unroll")                                                  \
            for (int j = 0; j < 4; j++) {                                      \
                int kk = (k0) + ch * 8 + 2 * j;                                \
                float a0 = eluf(hv[2*j]   + fmaf(zb, s_wz[kk],   s_b1[kk]));   \
                float a1v = eluf(hv[2*j+1] + fmaf(zb, s_wz[kk+1], s_b1[kk+1]));\
                __nv_bfloat16 hh0, ll0, hh1, ll1;                              \
                hilo(a0, hh0, ll0); hilo(a1v, hh1, ll1);                       \
                __nv_bfloat162 ph; ph.x = hh0; ph.y = hh1;                     \
                __nv_bfloat162 pl; pl.x = ll0; pl.y = ll1;                     \
                hp[j] = *(uint32_t*)&ph; lp[j] = *(uint32_t*)&pl;              \
            }                                                                  \
            uint32_t so = (uint32_t)(r * ROWB + ch * 16);                      \
            *(uint4*)(sm + stoff + 0 * MAT_BYTES + so) =                       \
                make_uint4(hp[0], hp[1], hp[2], hp[3]);                        \
            *(uint4*)(sm + stoff + 1 * MAT_BYTES + so) =                       \
                make_uint4(lp[0], lp[1], lp[2], lp[3]);                        \
        }                                                                      \
    } while (0)

#define BS_LOAD(stage, k0)                                                     \
    do {                                                                       \
        uint32_t st = sb + (uint32_t)(stage)*STG_BYTES;                        \
        if (EPI == 2) {                                                        \
            A_COMPUTE(stage, k0);                                              \
        } else {                                                               \
            _Pragma("unroll")                                                  \
            for (int t = 0; t < 2; t++) {                                      \
                int ci = tid + t * 256;                                        \
                int r = ci >> 2, ch = ci & 3;                                  \
                uint32_t so = (uint32_t)(r * ROWB + ch * 16);                  \
                size_t goA = (size_t)(mBase + r) * lda + (k0) + ch * 8;        \
                CP16(st + 0 * MAT_BYTES + so, ahiz + goA);                     \
                CP16(st + 1 * MAT_BYTES + so, aloz + goA);                     \
            }                                                                  \
        }                                                                      \
        _Pragma("unroll")                                                      \
        for (int t = 0; t < 2; t++) {                                          \
            int ci = tid + t * 256;                                            \
            int r = ci >> 2, ch = ci & 3;                                      \
            uint32_t so = (uint32_t)(r * ROWB + ch * 16);                      \
            size_t goB = (size_t)(nBase + r) * ldb + (k0) + ch * 8;            \
            CP16(st + 2 * MAT_BYTES + so, bhi + goB);                          \
            CP16(st + 3 * MAT_BYTES + so, blo + goB);                          \
        }                                                                      \
    } while (0)

    BS_LOAD(0, 0);
    CP_COMMIT();

#pragma unroll 1
    for (int it = 0; it < NIT; it++) {
        if (it + 1 < NIT) {
            BS_LOAD((it + 1) & 1, (it + 1) * BK);
            CP_COMMIT();
            CP_WAIT1();
        } else {
            CP_WAIT0();
        }
        __syncthreads();

        uint32_t st = sb + (uint32_t)(it & 1) * STG_BYTES;
        uint32_t aH = st + 0 * MAT_BYTES + (uint32_t)(warpM * 64) * ROWB + laneOff;
        uint32_t aL = st + 1 * MAT_BYTES + (uint32_t)(warpM * 64) * ROWB + laneOff;
        uint32_t bH = st + 2 * MAT_BYTES + (uint32_t)(warpN * 32) * ROWB + laneOff;
        uint32_t bL = st + 3 * MAT_BYTES + (uint32_t)(warpN * 32) * ROWB + laneOff;

#pragma unroll
        for (int ks = 0; ks < 2; ks++) {
            const uint32_t kb = ks * 32;
            uint32_t ah[4][4], al[4][4], bh[2][4], bl[2][4];
#pragma unroll
            for (int mt = 0; mt < 4; mt++) {
                ldmx4(ah[mt], aH + (uint32_t)(mt * 16) * ROWB + kb);
                ldmx4(al[mt], aL + (uint32_t)(mt * 16) * ROWB + kb);
            }
#pragma unroll
            for (int p = 0; p < 2; p++) {
                ldmx4(bh[p], bH + (uint32_t)(p * 16) * ROWB + kb);
                ldmx4(bl[p], bL + (uint32_t)(p * 16) * ROWB + kb);
            }
#pragma unroll
            for (int mt = 0; mt < 4; mt++) {
#pragma unroll
                for (int nt = 0; nt < 4; nt++) {
                    const int p = nt >> 1, q = nt & 1;
                    mma16816(acc[mt][nt], ah[mt], bh[p][q], bh[p][q + 2]);
                    mma16816(acc[mt][nt], ah[mt], bl[p][q], bl[p][q + 2]);
                    mma16816(acc[mt][nt], al[mt], bh[p][q], bh[p][q + 2]);
                }
            }
        }
        __syncthreads();
    }
#undef BS_LOAD
#undef A_COMPUTE

    if (EPI == 2) {
        const float* b2z = b2 + (size_t)blockIdx.z * HDIM;
        const float* w3z = W3 + (size_t)blockIdx.z * HDIM;
        const float b3d = b3[blockIdx.z];
        const bool joint = (blockIdx.y < 4);
#pragma unroll
        for (int mt = 0; mt < 4; mt++) {
            float s0 = 0.f, s1 = 0.f;
#pragma unroll
            for (int nt = 0; nt < 4; nt++) {
                int n0 = warpN * 32 + nt * 8 + (lane & 3) * 2;
                float w0 = __ldg(w3z + n0), w1 = __ldg(w3z + n0 + 1);
                float c0 = __ldg(b2z + n0), c1 = __ldg(b2z + n0 + 1);
                s0 += eluf(acc[mt][nt][0] + c0) * w0 + eluf(acc[mt][nt][1] + c1) * w1;
                s1 += eluf(acc[mt][nt][2] + c0) * w0 + eluf(acc[mt][nt][3] + c1) * w1;
            }
            s0 += __shfl_xor_sync(0xffffffffu, s0, 1);
            s0 += __shfl_xor_sync(0xffffffffu, s0, 2);
            s1 += __shfl_xor_sync(0xffffffffu, s1, 1);
            s1 += __shfl_xor_sync(0xffffffffu, s1, 2);
            if ((lane & 3) == 0) {
                int r0 = warpM * 64 + mt * 16 + (lane >> 2);
                red[r0][warpN] = s0;
                red[r0 + 8][warpN] = s1;
            }
        }
        __syncthreads();
        float val = 0.f;
        if (tid < 128) {
            float s = red[tid][0] + red[tid][1] + red[tid][2] + red[tid][3] + b3d;
            val = joint ? s : expf(s);
        }
#pragma unroll
        for (int off = 16; off; off >>= 1)
            val += __shfl_xor_sync(0xffffffffu, val, off);
        if (lane == 0) wr[wid] = val;
        __syncthreads();
        if (tid == 0) {
            float s = wr[0] + wr[1] + wr[2] + wr[3];
            int slot = blockIdx.z * 8 + blockIdx.y;
            if (joint) { g_js[slot] = s; g_es[slot] = 0.f; }
            else       { g_js[slot] = 0.f; g_es[slot] = s; }
        }
        return;
    }

#pragma unroll
    for (int mt = 0; mt < 4; mt++) {
        int m0 = mBase + warpM * 64 + mt * 16 + (lane >> 2);
#pragma unroll
        for (int nt = 0; nt < 4; nt++) {
            int n0 = nBase + warpN * 32 + nt * 8 + (lane & 3) * 2;
            if (EPI == 0) {
                float* Cz = C + (size_t)blockIdx.z * sCz;
                *(float2*)(Cz + (size_t)m0 * ldc + n0) =
                    make_float2(acc[mt][nt][0], acc[mt][nt][1]);
                *(float2*)(Cz + (size_t)(m0 + 8) * ldc + n0) =
                    make_float2(acc[mt][nt][2], acc[mt][nt][3]);
            } else if (EPI == 1) {
                float bv0 = bias[n0], bv1 = bias[n0 + 1];
                float u0 = eluf(acc[mt][nt][0] + bv0);
                float u1 = eluf(acc[mt][nt][1] + bv1);
                float u2 = eluf(acc[mt][nt][2] + bv0);
                float u3 = eluf(acc[mt][nt][3] + bv1);
                __nv_bfloat16 h0, h1, h2, h3, l0, l1, l2, l3;
                hilo(u0, h0, l0); hilo(u1, h1, l1);
                hilo(u2, h2, l2); hilo(u3, h3, l3);
                __nv_bfloat162 vh, vl;
                vh.x = h0; vh.y = h1; vl.x = l0; vl.y = l1;
                *(__nv_bfloat162*)(Chi + (size_t)m0 * ldc + n0) = vh;
                *(__nv_bfloat162*)(Clo + (size_t)m0 * ldc + n0) = vl;
                vh.x = h2; vh.y = h3; vl.x = l2; vl.y = l3;
                *(__nv_bfloat162*)(Chi + (size_t)(m0 + 8) * ldc + n0) = vh;
                *(__nv_bfloat162*)(Clo + (size_t)(m0 + 8) * ldc + n0) = vl;
            }
        }
    }
}

__global__ void finalize_kernel(float* __restrict__ out)
{
    int t = threadIdx.x;
    float acc = 0.f;
    for (int d = t; d < DDIM; d += 32) {
        float js = 0.f, es = 0.f;
#pragma unroll
        for (int c = 0; c < 8; c++) { js += g_js[d * 8 + c]; es += g_es[d * 8 + c]; }
        acc += js * (1.f / BB) - logf(es * (1.f / BB));
    }
#pragma unroll
    for (int off = 16; off; off >>= 1)
        acc += __shfl_xor_sync(0xffffffffu, acc, off);
    if (t == 0) out[0] = -acc * (1.f / DDIM);
}

// ---------------------------------------------------------------------------
extern "C" void kernel_launch(void* const* d_in, const int* in_sizes, int n_in,
                              void* d_out, int out_size)
{
    const float* x   = (const float*)d_in[0];
    const float* z   = (const float*)d_in[1];
    const int*   perm= (const int*)  d_in[2];
    const float* Wg1 = (const float*)d_in[3];
    const float* bg1 = (const float*)d_in[4];
    const float* Wg2 = (const float*)d_in[5];
    const float* bg2 = (const float*)d_in[6];
    const float* Wh  = (const float*)d_in[7];
    const float* Wz  = (const float*)d_in[8];
    const float* b1  = (const float*)d_in[9];
    const float* W2  = (const float*)d_in[10];
    const float* b2  = (const float*)d_in[11];
    const float* W3  = (const float*)d_in[12];
    const float* b3  = (const float*)d_in[13];

    __nv_bfloat16 *h1hi, *h1lo, *wg2thi, *wg2tlo, *hhi, *hlo, *whthi, *whtlo;
    __nv_bfloat16 *w2thi, *w2tlo;
    float* hwh;
    cudaGetSymbolAddress((void**)&h1hi,   g_h1hi);
    cudaGetSymbolAddress((void**)&h1lo,   g_h1lo);
    cudaGetSymbolAddress((void**)&wg2thi, g_wg2thi);
    cudaGetSymbolAddress((void**)&wg2tlo, g_wg2tlo);
    cudaGetSymbolAddress((void**)&hhi,    g_hhi);
    cudaGetSymbolAddress((void**)&hlo,    g_hlo);
    cudaGetSymbolAddress((void**)&whthi,  g_whthi);
    cudaGetSymbolAddress((void**)&whtlo,  g_whtlo);
    cudaGetSymbolAddress((void**)&w2thi,  g_w2thi);
    cudaGetSymbolAddress((void**)&w2tlo,  g_w2tlo);
    cudaGetSymbolAddress((void**)&hwh,    g_hWh);

    // K1 (R9 config) + piggybacked weight conversion on 16 extra CTAs
    cudaFuncSetAttribute(gemm_k1_kernel,
                         cudaFuncAttributeMaxDynamicSharedMemorySize, K1_SMEM);
    gemm_k1_kernel<<<dim3(G1D / K1_BN, BB / BM, K1_KS + 1), 256, K1_SMEM>>>(
        x, Wg1, Wg2, Wh, W2);
    reduce_h1_kernel<<<(BB * G1D) / 4 / 256, 256>>>(bg1);

    cudaFuncSetAttribute(gemm_bs<0>,
                         cudaFuncAttributeMaxDynamicSharedMemorySize, GEMM_SMEM);
    cudaFuncSetAttribute(gemm_bs<1>,
                         cudaFuncAttributeMaxDynamicSharedMemorySize, GEMM_SMEM);
    cudaFuncSetAttribute(gemm_bs<2>,
                         cudaFuncAttributeMaxDynamicSharedMemorySize, GEMM_SMEM);

    // K2: h = elu(h1 @ Wg2 + bg2) -> bf16 hi/lo
    gemm_bs<1><<<dim3(PDIM / 128, BB / BM, 1), 256, GEMM_SMEM>>>(
        h1hi, h1lo, G1D, 0, wg2thi, wg2tlo, G1D, 0,
        nullptr, hhi, hlo, bg2, PDIM, 0, G1D,
        nullptr, nullptr, nullptr, nullptr, nullptr, nullptr, nullptr, nullptr);

    // K3: hWh[d] = h @ WhT[d]  (fp32)
    gemm_bs<0><<<dim3(1, BB / BM, DDIM), 256, GEMM_SMEM>>>(
        hhi, hlo, PDIM, 0, whthi, whtlo, PDIM, (long)HDIM * PDIM,
        hwh, nullptr, nullptr, nullptr, HDIM, (long)BB * HDIM, PDIM,
        nullptr, nullptr, nullptr, nullptr, nullptr, nullptr, nullptr, nullptr);

    // head: fused a1 compute + a2 GEMM + scores + reductions
    gemm_bs<2><<<dim3(1, (2 * BB) / BM, DDIM), 256, GEMM_SMEM>>>(
        nullptr, nullptr, HDIM, 0,
        w2thi, w2tlo, HDIM, (long)HDIM * HDIM,
        nullptr, nullptr, nullptr, nullptr, HDIM, 0, HDIM,
        b2, W3, b3, hwh, z, perm, Wz, b1);

    finalize_kernel<<<1, 32>>>((float*)d_out);
}

// round 15
// speedup vs baseline: 1.8527x; 1.8527x over previous
#include <cuda_runtime.h>
#include <cuda_bf16.h>
#include <math.h>
#include <stdint.h>

// Problem dims
#define BB   512
#define XDIM 32768
#define PDIM 512
#define DDIM 64
#define HDIM 128
#define G1D  1024

// Shared HMMA config
#define BM 128
#define BK 32
#define PITCH 40
#define ROWB (PITCH * 2)        // 80

// gemm_bs (BN=128)
#define MAT_BYTES (128 * ROWB)        // 10240
#define STG_BYTES (4 * MAT_BYTES)     // 40960
#define GEMM_SMEM (2 * STG_BYTES)     // 81920

// K1 (BM=128, BN=256, KS=8, 3-stage, fused fp32->hi/lo loader)  — R9 config
#define K1_BN 256
#define K1_KS 8
#define K1_KCHUNK (XDIM / K1_KS)      // 4096
#define K1_NIT (K1_KCHUNK / BK)       // 128
#define K1_MAT_A 10240                // 128 rows x 80B
#define K1_B_PITCH 528                // 256 n x 2B + 16B pad
#define K1_MAT_B (32 * K1_B_PITCH)    // 16896
#define K1_AH 0
#define K1_AL K1_MAT_A
#define K1_BH (2 * K1_MAT_A)
#define K1_BL (2 * K1_MAT_A + K1_MAT_B)
#define K1_STG (2 * K1_MAT_A + 2 * K1_MAT_B)   // 54272
#define K1_SMEM (3 * K1_STG)                   // 162816

// ---------------- device scratch ----------------
__device__ float g_part[K1_KS * BB * G1D];     // 16 MB
__device__ __nv_bfloat16 g_h1hi[BB * G1D];
__device__ __nv_bfloat16 g_h1lo[BB * G1D];
__device__ __nv_bfloat16 g_wg2thi[PDIM * G1D];
__device__ __nv_bfloat16 g_wg2tlo[PDIM * G1D];
__device__ __nv_bfloat16 g_hhi[BB * PDIM];
__device__ __nv_bfloat16 g_hlo[BB * PDIM];
__device__ __nv_bfloat16 g_whthi[DDIM * HDIM * PDIM];
__device__ __nv_bfloat16 g_whtlo[DDIM * HDIM * PDIM];
__device__ float g_hWh[DDIM * BB * HDIM];
__device__ __nv_bfloat16 g_w2thi[DDIM * HDIM * HDIM];
__device__ __nv_bfloat16 g_w2tlo[DDIM * HDIM * HDIM];
__device__ float g_js[DDIM * 8];
__device__ float g_es[DDIM * 8];

__device__ __forceinline__ float eluf(float x) {
    return x > 0.f ? x : expm1f(x);
}
__device__ __forceinline__ uint32_t smem_u32(const void* p) {
    uint32_t a;
    asm("{ .reg .u64 t; cvta.to.shared.u64 t, %1; cvt.u32.u64 %0, t; }"
        : "=r"(a) : "l"(p));
    return a;
}
#define CP16(dst, src) \
    asm volatile("cp.async.cg.shared.global [%0], [%1], 16;" \
                 :: "r"(dst), "l"(src) : "memory")
#define CP_COMMIT() asm volatile("cp.async.commit_group;" ::: "memory")
#define CP_WAIT1()  asm volatile("cp.async.wait_group 1;" ::: "memory")
#define CP_WAIT0()  asm volatile("cp.async.wait_group 0;" ::: "memory")

__device__ __forceinline__ void ldmx4(uint32_t* r, uint32_t addr) {
    asm volatile("ldmatrix.sync.aligned.m8n8.x4.shared.b16 {%0,%1,%2,%3}, [%4];"
                 : "=r"(r[0]), "=r"(r[1]), "=r"(r[2]), "=r"(r[3]) : "r"(addr));
}
__device__ __forceinline__ void ldmx4t(uint32_t* r, uint32_t addr) {
    asm volatile("ldmatrix.sync.aligned.m8n8.x4.trans.shared.b16 {%0,%1,%2,%3}, [%4];"
                 : "=r"(r[0]), "=r"(r[1]), "=r"(r[2]), "=r"(r[3]) : "r"(addr));
}
__device__ __forceinline__ void mma16816(float* c, const uint32_t* a,
                                         uint32_t b0, uint32_t b1) {
    asm volatile(
        "mma.sync.aligned.m16n8k16.row.col.f32.bf16.bf16.f32 "
        "{%0,%1,%2,%3}, {%4,%5,%6,%7}, {%8,%9}, {%0,%1,%2,%3};"
        : "+f"(c[0]), "+f"(c[1]), "+f"(c[2]), "+f"(c[3])
        : "r"(a[0]), "r"(a[1]), "r"(a[2]), "r"(a[3]), "r"(b0), "r"(b1));
}
__device__ __forceinline__ void hilo(float v, __nv_bfloat16& h, __nv_bfloat16& l) {
    h = __float2bfloat16(v);
    l = __float2bfloat16(v - __bfloat162float(h));
}
// pack 8 fp32 -> 16B hi + 16B lo
__device__ __forceinline__ void pack8(const float* v, uint4& H, uint4& L) {
    uint32_t hw[4], lw[4];
#pragma unroll
    for (int j = 0; j < 4; j++) {
        __nv_bfloat16 h0, l0, h1, l1;
        hilo(v[2 * j], h0, l0);
        hilo(v[2 * j + 1], h1, l1);
        __nv_bfloat162 ph; ph.x = h0; ph.y = h1;
        __nv_bfloat162 pl; pl.x = l0; pl.y = l1;
        hw[j] = *(uint32_t*)&ph;
        lw[j] = *(uint32_t*)&pl;
    }
    H = make_uint4(hw[0], hw[1], hw[2], hw[3]);
    L = make_uint4(lw[0], lw[1], lw[2], lw[3]);
}

// ---------------- conversions (small weights only) ----------------
__global__ void transconv_kernel(const float* __restrict__ src,
                                 __nv_bfloat16* __restrict__ dhi,
                                 __nv_bfloat16* __restrict__ dlo,
                                 int R, int C) {
    __shared__ float s[32][33];
    const size_t zoff = (size_t)blockIdx.z * R * C;
    const int rt = blockIdx.y * 32, ct = blockIdx.x * 32;
    const int tx = threadIdx.x & 31, ty = threadIdx.x >> 5;
    for (int r = ty; r < 32; r += 8)
        s[r][tx] = src[zoff + (size_t)(rt + r) * C + ct + tx];
    __syncthreads();
    for (int c = ty; c < 32; c += 8) {
        float v = s[tx][c];
        __nv_bfloat16 h, l;
        hilo(v, h, l);
        dhi[zoff + (size_t)(ct + c) * R + rt + tx] = h;
        dlo[zoff + (size_t)(ct + c) * R + rt + tx] = l;
    }
}

// ---------------- K1: fused-convert bf16-split HMMA (R9 exact) --------------
__global__ void __launch_bounds__(256, 1) gemm_k1_kernel(
    const float* __restrict__ x, const float* __restrict__ Wg1)
{
    extern __shared__ char sm[];
    const uint32_t sb = smem_u32(sm);
    const int tid = threadIdx.x;
    const int lane = tid & 31;
    const int wid = tid >> 5;
    const int warpM = wid >> 2;   // 0..1 -> 64 rows
    const int warpN = wid & 3;    // 0..3 -> 64 cols

    const int nBase = blockIdx.x * K1_BN;
    const int mBase = blockIdx.y * BM;
    const int kBase = blockIdx.z * K1_KCHUNK;

    const uint32_t laneOffA =
        (uint32_t)(((lane & 7) + ((lane >> 3) & 1) * 8) * ROWB + (lane >> 4) * 16);
    const uint32_t laneOffB =
        (uint32_t)(((lane & 7) + ((lane >> 3) & 1) * 8) * K1_B_PITCH +
                   (lane >> 4) * 16);

    float acc[4][8][4];
#pragma unroll
    for (int i = 0; i < 4; i++)
#pragma unroll
        for (int j = 0; j < 8; j++)
#pragma unroll
            for (int k = 0; k < 4; k++) acc[i][j][k] = 0.f;

    float pfA[2][8], pfB[4][8];

    auto LDG_STAGE = [&](int itn) {
        const int k0 = kBase + itn * BK;
#pragma unroll
        for (int t = 0; t < 2; t++) {
            int u = tid + t * 256;
            int m = u >> 2, kc = (u & 3) * 8;
            const float4* s = (const float4*)(x + (size_t)(mBase + m) * XDIM + k0 + kc);
            float4 v0 = __ldg(s), v1 = __ldg(s + 1);
            pfA[t][0] = v0.x; pfA[t][1] = v0.y; pfA[t][2] = v0.z; pfA[t][3] = v0.w;
            pfA[t][4] = v1.x; pfA[t][5] = v1.y; pfA[t][6] = v1.z; pfA[t][7] = v1.w;
        }
#pragma unroll
        for (int t = 0; t < 4; t++) {
            int u = tid + t * 256;
            int k = u >> 5, n8 = (u & 31) * 8;
            const float4* s = (const float4*)(Wg1 + (size_t)(k0 + k) * G1D + nBase + n8);
            float4 v0 = __ldg(s), v1 = __ldg(s + 1);
            pfB[t][0] = v0.x; pfB[t][1] = v0.y; pfB[t][2] = v0.z; pfB[t][3] = v0.w;
            pfB[t][4] = v1.x; pfB[t][5] = v1.y; pfB[t][6] = v1.z; pfB[t][7] = v1.w;
        }
    };
    auto STS_STAGE = [&](int stage) {
        char* st = sm + (size_t)stage * K1_STG;
#pragma unroll
        for (int t = 0; t < 2; t++) {
            int u = tid + t * 256;
            int m = u >> 2, kc = (u & 3) * 8;
            uint4 H, L;
            pack8(pfA[t], H, L);
            uint32_t so = (uint32_t)(m * ROWB + kc * 2);
            *(uint4*)(st + K1_AH + so) = H;
            *(uint4*)(st + K1_AL + so) = L;
        }
#pragma unroll
        for (int t = 0; t < 4; t++) {
            int u = tid + t * 256;
            int k = u >> 5, n8 = (u & 31) * 8;
            uint4 H, L;
            pack8(pfB[t], H, L);
            uint32_t so = (uint32_t)(k * K1_B_PITCH + n8 * 2);
            *(uint4*)(st + K1_BH + so) = H;
            *(uint4*)(st + K1_BL + so) = L;
        }
    };

    LDG_STAGE(0); STS_STAGE(0);
    LDG_STAGE(1); STS_STAGE(1);
    __syncthreads();

#pragma unroll 1
    for (int it = 0; it < K1_NIT; it++) {
        const bool pf = (it + 2 < K1_NIT);
        if (pf) LDG_STAGE(it + 2);

        uint32_t st = sb + (uint32_t)(it % 3) * K1_STG;
        uint32_t aH = st + K1_AH + (uint32_t)(warpM * 64) * ROWB + laneOffA;
        uint32_t aL = st + K1_AL + (uint32_t)(warpM * 64) * ROWB + laneOffA;
        uint32_t bH = st + K1_BH + (uint32_t)(warpN * 64) * 2 + laneOffB;
        uint32_t bL = st + K1_BL + (uint32_t)(warpN * 64) * 2 + laneOffB;

#pragma unroll
        for (int ks = 0; ks < 2; ks++) {
            const uint32_t kbA = ks * 32;
            const uint32_t kbB = ks * 16 * K1_B_PITCH;
            uint32_t ah[4][4], al[4][4];
#pragma unroll
            for (int mt = 0; mt < 4; mt++) {
                ldmx4(ah[mt], aH + (uint32_t)(mt * 16) * ROWB + kbA);
                ldmx4(al[mt], aL + (uint32_t)(mt * 16) * ROWB + kbA);
            }
#pragma unroll
            for (int p = 0; p < 4; p++) {
                uint32_t bh[4], bl[4];
                ldmx4t(bh, bH + (uint32_t)(p * 32) + kbB);
                ldmx4t(bl, bL + (uint32_t)(p * 32) + kbB);
#pragma unroll
                for (int mt = 0; mt < 4; mt++) {
                    mma16816(acc[mt][2 * p], ah[mt], bh[0], bh[1]);
                    mma16816(acc[mt][2 * p], ah[mt], bl[0], bl[1]);
                    mma16816(acc[mt][2 * p], al[mt], bh[0], bh[1]);
                    mma16816(acc[mt][2 * p + 1], ah[mt], bh[2], bh[3]);
                    mma16816(acc[mt][2 * p + 1], ah[mt], bl[2], bl[3]);
                    mma16816(acc[mt][2 * p + 1], al[mt], bh[2], bh[3]);
                }
            }
        }

        if (pf) STS_STAGE((it + 2) % 3);
        __syncthreads();
    }

    float* base = g_part + (size_t)blockIdx.z * (BB * G1D);
#pragma unroll
    for (int mt = 0; mt < 4; mt++) {
        int m0 = mBase + warpM * 64 + mt * 16 + (lane >> 2);
#pragma unroll
        for (int nt = 0; nt < 8; nt++) {
            int n0 = nBase + warpN * 64 + nt * 8 + (lane & 3) * 2;
            *(float2*)(base + (size_t)m0 * G1D + n0) =
                make_float2(acc[mt][nt][0], acc[mt][nt][1]);
            *(float2*)(base + (size_t)(m0 + 8) * G1D + n0) =
                make_float2(acc[mt][nt][2], acc[mt][nt][3]);
        }
    }
}

// partials -> h1 = elu(sum + bias), bf16 hi/lo (float4)
__global__ void reduce_h1_kernel(const float* __restrict__ bg1) {
    const int i4 = blockIdx.x * 256 + threadIdx.x;
    float4 s = make_float4(0.f, 0.f, 0.f, 0.f);
#pragma unroll
    for (int k = 0; k < K1_KS; k++) {
        float4 v = ((const float4*)g_part)[k * (BB * G1D / 4) + i4];
        s.x += v.x; s.y += v.y; s.z += v.z; s.w += v.w;
    }
    const int c0 = (i4 * 4) & (G1D - 1);
    float4 b = *(const float4*)(bg1 + c0);
    float u0 = eluf(s.x + b.x), u1 = eluf(s.y + b.y);
    float u2 = eluf(s.z + b.z), u3 = eluf(s.w + b.w);
    __nv_bfloat16 h0, h1, h2, h3, l0, l1, l2, l3;
    hilo(u0, h0, l0); hilo(u1, h1, l1); hilo(u2, h2, l2); hilo(u3, h3, l3);
    __nv_bfloat162 vh0, vh1, vl0, vl1;
    vh0.x = h0; vh0.y = h1; vh1.x = h2; vh1.y = h3;
    vl0.x = l0; vl0.y = l1; vl1.x = l2; vl1.y = l3;
    ((__nv_bfloat162*)g_h1hi)[2 * i4] = vh0;
    ((__nv_bfloat162*)g_h1hi)[2 * i4 + 1] = vh1;
    ((__nv_bfloat162*)g_h1lo)[2 * i4] = vl0;
    ((__nv_bfloat162*)g_h1lo)[2 * i4 + 1] = vl1;
}

// ---------------- unified bf16-split HMMA GEMM (BN=128) ----------------
template <int EPI>
__global__ void __launch_bounds__(256, 2) gemm_bs(
    const __nv_bfloat16* __restrict__ Ahi, const __nv_bfloat16* __restrict__ Alo,
    int lda, long sAz,
    const __nv_bfloat16* __restrict__ Bhi, const __nv_bfloat16* __restrict__ Blo,
    int ldb, long sBz,
    float* __restrict__ C, __nv_bfloat16* __restrict__ Chi,
    __nv_bfloat16* __restrict__ Clo,
    const float* __restrict__ bias, int ldc, long sCz, int K,
    const float* __restrict__ b2, const float* __restrict__ W3,
    const float* __restrict__ b3,
    const float* __restrict__ hwhp, const float* __restrict__ zv,
    const int* __restrict__ permp, const float* __restrict__ Wzp,
    const float* __restrict__ b1p)
{
    extern __shared__ char sm[];
    __shared__ float red[128][5];
    __shared__ float wr[8];
    __shared__ float s_wz[HDIM], s_b1[HDIM];
    const uint32_t sb = smem_u32(sm);
    const int tid = threadIdx.x;
    const int lane = tid & 31;
    const int wid = tid >> 5;
    const int warpM = wid >> 2;
    const int warpN = wid & 3;

    const int nBase = blockIdx.x * 128;
    const int mBase = blockIdx.y * BM;
    const __nv_bfloat16* ahiz = Ahi + (size_t)blockIdx.z * sAz;
    const __nv_bfloat16* aloz = Alo + (size_t)blockIdx.z * sAz;
    const __nv_bfloat16* bhi = Bhi + (size_t)blockIdx.z * sBz;
    const __nv_bfloat16* blo = Blo + (size_t)blockIdx.z * sBz;

    if (EPI == 2) {
        if (tid < HDIM) {
            s_wz[tid] = Wzp[(size_t)blockIdx.z * HDIM + tid];
            s_b1[tid] = b1p[(size_t)blockIdx.z * HDIM + tid];
        }
        __syncthreads();
    }

    const uint32_t laneOff =
        (uint32_t)(((lane & 7) + ((lane >> 3) & 1) * 8) * ROWB + (lane >> 4) * 16);
    const int NIT = K / BK;

    float acc[4][4][4];
#pragma unroll
    for (int i = 0; i < 4; i++)
#pragma unroll
        for (int j = 0; j < 4; j++)
#pragma unroll
            for (int k = 0; k < 4; k++) acc[i][j][k] = 0.f;

#define A_COMPUTE(stage, k0)                                                   \
    do {                                                                       \
        uint32_t stoff = (uint32_t)(stage) * STG_BYTES;                        \
        const float* hwh_d = hwhp + (size_t)blockIdx.z * BB * HDIM;            \
        _Pragma("unroll")                                                      \
        for (int t = 0; t < 2; t++) {                                          \
            int u = tid + t * 256;                                             \
            int r = u >> 2, ch = u & 3;                                        \
            int gm = mBase + r;                                                \
            int b = (gm < BB) ? gm : gm - BB;                                  \
            int src = (gm < BB) ? b : __ldg(permp + b);                        \
            float zb = __ldg(zv + (size_t)b * DDIM + blockIdx.z);              \
            const float* hr = hwh_d + (size_t)src * HDIM + (k0) + ch * 8;      \
            float4 v0 = __ldg((const float4*)hr);                              \
            float4 v1 = __ldg((const float4*)(hr + 4));                        \
            float hv[8] = {v0.x, v0.y, v0.z, v0.w, v1.x, v1.y, v1.z, v1.w};    \
            uint32_t hp[4], lp[4];                                             \
            _Pragma("unroll")                                                  \
            for (int j = 0; j < 4; j++) {                                      \
                int kk = (k0) + ch * 8 + 2 * j;                                \
                float a0 = eluf(hv[2*j]   + fmaf(zb, s_wz[kk],   s_b1[kk]));   \
                float a1v = eluf(hv[2*j+1] + fmaf(zb, s_wz[kk+1], s_b1[kk+1]));\
                __nv_bfloat16 hh0, ll0, hh1, ll1;                              \
                hilo(a0, hh0, ll0); hilo(a1v, hh1, ll1);                       \
                __nv_bfloat162 ph; ph.x = hh0; ph.y = hh1;                     \
                __nv_bfloat162 pl; pl.x = ll0; pl.y = ll1;                     \
                hp[j] = *(uint32_t*)&ph; lp[j] = *(uint32_t*)&pl;              \
            }                                                                  \
            uint32_t so = (uint32_t)(r * ROWB + ch * 16);                      \
            *(uint4*)(sm + stoff + 0 * MAT_BYTES + so) =                       \
                make_uint4(hp[0], hp[1], hp[2], hp[3]);                        \
            *(uint4*)(sm + stoff + 1 * MAT_BYTES + so) =                       \
                make_uint4(lp[0], lp[1], lp[2], lp[3]);                        \
        }                                                                      \
    } while (0)

#define BS_LOAD(stage, k0)                                                     \
    do {                                                                       \
        uint32_t st = sb + (uint32_t)(stage)*STG_BYTES;                        \
        if (EPI == 2) {                                                        \
            A_COMPUTE(stage, k0);                                              \
        } else {                                                               \
            _Pragma("unroll")                                                  \
            for (int t = 0; t < 2; t++) {                                      \
                int ci = tid + t * 256;                                        \
                int r = ci >> 2, ch = ci & 3;                                  \
                uint32_t so = (uint32_t)(r * ROWB + ch * 16);                  \
                size_t goA = (size_t)(mBase + r) * lda + (k0) + ch * 8;        \
                CP16(st + 0 * MAT_BYTES + so, ahiz + goA);                     \
                CP16(st + 1 * MAT_BYTES + so, aloz + goA);                     \
            }                                                                  \
        }                                                                      \
        _Pragma("unroll")                                                      \
        for (int t = 0; t < 2; t++) {                                          \
            int ci = tid + t * 256;                                            \
            int r = ci >> 2, ch = ci & 3;                                      \
            uint32_t so = (uint32_t)(r * ROWB + ch * 16);                      \
            size_t goB = (size_t)(nBase + r) * ldb + (k0) + ch * 8;            \
            CP16(st + 2 * MAT_BYTES + so, bhi + goB);                          \
            CP16(st + 3 * MAT_BYTES + so, blo + goB);                          \
        }                                                                      \
    } while (0)

    BS_LOAD(0, 0);
    CP_COMMIT();

#pragma unroll 1
    for (int it = 0; it < NIT; it++) {
        if (it + 1 < NIT) {
            BS_LOAD((it + 1) & 1, (it + 1) * BK);
            CP_COMMIT();
            CP_WAIT1();
        } else {
            CP_WAIT0();
        }
        __syncthreads();

        uint32_t st = sb + (uint32_t)(it & 1) * STG_BYTES;
        uint32_t aH = st + 0 * MAT_BYTES + (uint32_t)(warpM * 64) * ROWB + laneOff;
        uint32_t aL = st + 1 * MAT_BYTES + (uint32_t)(warpM * 64) * ROWB + laneOff;
        uint32_t bH = st + 2 * MAT_BYTES + (uint32_t)(warpN * 32) * ROWB + laneOff;
        uint32_t bL = st + 3 * MAT_BYTES + (uint32_t)(warpN * 32) * ROWB + laneOff;

#pragma unroll
        for (int ks = 0; ks < 2; ks++) {
            const uint32_t kb = ks * 32;
            uint32_t ah[4][4], al[4][4], bh[2][4], bl[2][4];
#pragma unroll
            for (int mt = 0; mt < 4; mt++) {
                ldmx4(ah[mt], aH + (uint32_t)(mt * 16) * ROWB + kb);
                ldmx4(al[mt], aL + (uint32_t)(mt * 16) * ROWB + kb);
            }
#pragma unroll
            for (int p = 0; p < 2; p++) {
                ldmx4(bh[p], bH + (uint32_t)(p * 16) * ROWB + kb);
                ldmx4(bl[p], bL + (uint32_t)(p * 16) * ROWB + kb);
            }
#pragma unroll
            for (int mt = 0; mt < 4; mt++) {
#pragma unroll
                for (int nt = 0; nt < 4; nt++) {
                    const int p = nt >> 1, q = nt & 1;
                    mma16816(acc[mt][nt], ah[mt], bh[p][q], bh[p][q + 2]);
                    mma16816(acc[mt][nt], ah[mt], bl[p][q], bl[p][q + 2]);
                    mma16816(acc[mt][nt], al[mt], bh[p][q], bh[p][q + 2]);
                }
            }
        }
        __syncthreads();
    }
#undef BS_LOAD
#undef A_COMPUTE

    if (EPI == 2) {
        const float* b2z = b2 + (size_t)blockIdx.z * HDIM;
        const float* w3z = W3 + (size_t)blockIdx.z * HDIM;
        const float b3d = b3[blockIdx.z];
        const bool joint = (blockIdx.y < 4);
#pragma unroll
        for (int mt = 0; mt < 4; mt++) {
            float s0 = 0.f, s1 = 0.f;
#pragma unroll
            for (int nt = 0; nt < 4; nt++) {
                int n0 = warpN * 32 + nt * 8 + (lane & 3) * 2;
                float w0 = __ldg(w3z + n0), w1 = __ldg(w3z + n0 + 1);
                float c0 = __ldg(b2z + n0), c1 = __ldg(b2z + n0 + 1);
                s0 += eluf(acc[mt][nt][0] + c0) * w0 + eluf(acc[mt][nt][1] + c1) * w1;
                s1 += eluf(acc[mt][nt][2] + c0) * w0 + eluf(acc[mt][nt][3] + c1) * w1;
            }
            s0 += __shfl_xor_sync(0xffffffffu, s0, 1);
            s0 += __shfl_xor_sync(0xffffffffu, s0, 2);
            s1 += __shfl_xor_sync(0xffffffffu, s1, 1);
            s1 += __shfl_xor_sync(0xffffffffu, s1, 2);
            if ((lane & 3) == 0) {
                int r0 = warpM * 64 + mt * 16 + (lane >> 2);
                red[r0][warpN] = s0;
                red[r0 + 8][warpN] = s1;
            }
        }
        __syncthreads();
        float val = 0.f;
        if (tid < 128) {
            float s = red[tid][0] + red[tid][1] + red[tid][2] + red[tid][3] + b3d;
            val = joint ? s : expf(s);
        }
#pragma unroll
        for (int off = 16; off; off >>= 1)
            val += __shfl_xor_sync(0xffffffffu, val, off);
        if (lane == 0) wr[wid] = val;
        __syncthreads();
        if (tid == 0) {
            float s = wr[0] + wr[1] + wr[2] + wr[3];
            int slot = blockIdx.z * 8 + blockIdx.y;
            if (joint) { g_js[slot] = s; g_es[slot] = 0.f; }
            else       { g_js[slot] = 0.f; g_es[slot] = s; }
        }
        return;
    }

#pragma unroll
    for (int mt = 0; mt < 4; mt++) {
        int m0 = mBase + warpM * 64 + mt * 16 + (lane >> 2);
#pragma unroll
        for (int nt = 0; nt < 4; nt++) {
            int n0 = nBase + warpN * 32 + nt * 8 + (lane & 3) * 2;
            if (EPI == 0) {
                float* Cz = C + (size_t)blockIdx.z * sCz;
                *(float2*)(Cz + (size_t)m0 * ldc + n0) =
                    make_float2(acc[mt][nt][0], acc[mt][nt][1]);
                *(float2*)(Cz + (size_t)(m0 + 8) * ldc + n0) =
                    make_float2(acc[mt][nt][2], acc[mt][nt][3]);
            } else if (EPI == 1) {
                float bv0 = bias[n0], bv1 = bias[n0 + 1];
                float u0 = eluf(acc[mt][nt][0] + bv0);
                float u1 = eluf(acc[mt][nt][1] + bv1);
                float u2 = eluf(acc[mt][nt][2] + bv0);
                float u3 = eluf(acc[mt][nt][3] + bv1);
                __nv_bfloat16 h0, h1, h2, h3, l0, l1, l2, l3;
                hilo(u0, h0, l0); hilo(u1, h1, l1);
                hilo(u2, h2, l2); hilo(u3, h3, l3);
                __nv_bfloat162 vh, vl;
                vh.x = h0; vh.y = h1; vl.x = l0; vl.y = l1;
                *(__nv_bfloat162*)(Chi + (size_t)m0 * ldc + n0) = vh;
                *(__nv_bfloat162*)(Clo + (size_t)m0 * ldc + n0) = vl;
                vh.x = h2; vh.y = h3; vl.x = l2; vl.y = l3;
                *(__nv_bfloat162*)(Chi + (size_t)(m0 + 8) * ldc + n0) = vh;
                *(__nv_bfloat162*)(Clo + (size_t)(m0 + 8) * ldc + n0) = vl;
            }
        }
    }
}

__global__ void finalize_kernel(float* __restrict__ out)
{
    int t = threadIdx.x;
    float acc = 0.f;
    for (int d = t; d < DDIM; d += 32) {
        float js = 0.f, es = 0.f;
#pragma unroll
        for (int c = 0; c < 8; c++) { js += g_js[d * 8 + c]; es += g_es[d * 8 + c]; }
        acc += js * (1.f / BB) - logf(es * (1.f / BB));
    }
#pragma unroll
    for (int off = 16; off; off >>= 1)
        acc += __shfl_xor_sync(0xffffffffu, acc, off);
    if (t == 0) out[0] = -acc * (1.f / DDIM);
}

// ---------------------------------------------------------------------------
extern "C" void kernel_launch(void* const* d_in, const int* in_sizes, int n_in,
                              void* d_out, int out_size)
{
    const float* x   = (const float*)d_in[0];
    const float* z   = (const float*)d_in[1];
    const int*   perm= (const int*)  d_in[2];
    const float* Wg1 = (const float*)d_in[3];
    const float* bg1 = (const float*)d_in[4];
    const float* Wg2 = (const float*)d_in[5];
    const float* bg2 = (const float*)d_in[6];
    const float* Wh  = (const float*)d_in[7];
    const float* Wz  = (const float*)d_in[8];
    const float* b1  = (const float*)d_in[9];
    const float* W2  = (const float*)d_in[10];
    const float* b2  = (const float*)d_in[11];
    const float* W3  = (const float*)d_in[12];
    const float* b3  = (const float*)d_in[13];

    __nv_bfloat16 *h1hi, *h1lo, *wg2thi, *wg2tlo, *hhi, *hlo, *whthi, *whtlo;
    __nv_bfloat16 *w2thi, *w2tlo;
    float* hwh;
    cudaGetSymbolAddress((void**)&h1hi,   g_h1hi);
    cudaGetSymbolAddress((void**)&h1lo,   g_h1lo);
    cudaGetSymbolAddress((void**)&wg2thi, g_wg2thi);
    cudaGetSymbolAddress((void**)&wg2tlo, g_wg2tlo);
    cudaGetSymbolAddress((void**)&hhi,    g_hhi);
    cudaGetSymbolAddress((void**)&hlo,    g_hlo);
    cudaGetSymbolAddress((void**)&whthi,  g_whthi);
    cudaGetSymbolAddress((void**)&whtlo,  g_whtlo);
    cudaGetSymbolAddress((void**)&w2thi,  g_w2thi);
    cudaGetSymbolAddress((void**)&w2tlo,  g_w2tlo);
    cudaGetSymbolAddress((void**)&hwh,    g_hWh);

    // small-weight conversions
    transconv_kernel<<<dim3(PDIM / 32, G1D / 32, 1), 256>>>(Wg2, wg2thi, wg2tlo,
                                                            G1D, PDIM);
    transconv_kernel<<<dim3(HDIM / 32, PDIM / 32, DDIM), 256>>>(Wh, whthi, whtlo,
                                                                PDIM, HDIM);
    transconv_kernel<<<dim3(HDIM / 32, HDIM / 32, DDIM), 256>>>(W2, w2thi, w2tlo,
                                                                HDIM, HDIM);

    // K1: fused fp32->hi/lo loader + bf16-split HMMA
    cudaFuncSetAttribute(gemm_k1_kernel,
                         cudaFuncAttributeMaxDynamicSharedMemorySize, K1_SMEM);
    gemm_k1_kernel<<<dim3(G1D / K1_BN, BB / BM, K1_KS), 256, K1_SMEM>>>(x, Wg1);
    reduce_h1_kernel<<<(BB * G1D) / 4 / 256, 256>>>(bg1);

    cudaFuncSetAttribute(gemm_bs<0>,
                         cudaFuncAttributeMaxDynamicSharedMemorySize, GEMM_SMEM);
    cudaFuncSetAttribute(gemm_bs<1>,
                         cudaFuncAttributeMaxDynamicSharedMemorySize, GEMM_SMEM);
    cudaFuncSetAttribute(gemm_bs<2>,
                         cudaFuncAttributeMaxDynamicSharedMemorySize, GEMM_SMEM);

    // K2: h = elu(h1 @ Wg2 + bg2) -> bf16 hi/lo
    gemm_bs<1><<<dim3(PDIM / 128, BB / BM, 1), 256, GEMM_SMEM>>>(
        h1hi, h1lo, G1D, 0, wg2thi, wg2tlo, G1D, 0,
        nullptr, hhi, hlo, bg2, PDIM, 0, G1D,
        nullptr, nullptr, nullptr, nullptr, nullptr, nullptr, nullptr, nullptr);

    // K3: hWh[d] = h @ WhT[d]  (fp32)
    gemm_bs<0><<<dim3(1, BB / BM, DDIM), 256, GEMM_SMEM>>>(
        hhi, hlo, PDIM, 0, whthi, whtlo, PDIM, (long)HDIM * PDIM,
        hwh, nullptr, nullptr, nullptr, HDIM, (long)BB * HDIM, PDIM,
        nullptr, nullptr, nullptr, nullptr, nullptr, nullptr, nullptr, nullptr);

    // head: fused a1 compute + a2 GEMM + scores + reductions
    gemm_bs<2><<<dim3(1, (2 * BB) / BM, DDIM), 256, GEMM_SMEM>>>(
        nullptr, nullptr, HDIM, 0,
        w2thi, w2tlo, HDIM, (long)HDIM * HDIM,
        nullptr, nullptr, nullptr, nullptr, HDIM, 0, HDIM,
        b2, W3, b3, hwh, z, perm, Wz, b1);

    finalize_kernel<<<1, 32>>>((float*)d_out);
}

// round 16
// speedup vs baseline: 1.8992x; 1.0251x over previous
#include <cuda_runtime.h>
#include <cuda_bf16.h>
#include <math.h>
#include <stdint.h>

// Problem dims
#define BB   512
#define XDIM 32768
#define PDIM 512
#define DDIM 64
#define HDIM 128
#define G1D  1024

// Shared HMMA config
#define BM 128
#define BK 32
#define PITCH 40
#define ROWB (PITCH * 2)        // 80

// gemm_bs (BN=128)
#define MAT_BYTES (128 * ROWB)        // 10240
#define STG_BYTES (4 * MAT_BYTES)     // 40960
#define GEMM_SMEM (2 * STG_BYTES)     // 81920

// K1 (BM=128, BN=256, KS=8, 3-stage, fused fp32->hi/lo loader)  — R9 config
#define K1_BN 256
#define K1_KS 8
#define K1_KCHUNK (XDIM / K1_KS)      // 4096
#define K1_NIT (K1_KCHUNK / BK)       // 128
#define K1_MAT_A 10240                // 128 rows x 80B
#define K1_B_PITCH 528                // 256 n x 2B + 16B pad
#define K1_MAT_B (32 * K1_B_PITCH)    // 16896
#define K1_AH 0
#define K1_AL K1_MAT_A
#define K1_BH (2 * K1_MAT_A)
#define K1_BL (2 * K1_MAT_A + K1_MAT_B)
#define K1_STG (2 * K1_MAT_A + 2 * K1_MAT_B)   // 54272
#define K1_SMEM (3 * K1_STG)                   // 162816

// merged conversion tiles (32 rows x 128 cols each)
#define CT_WG2 128                    // 32 x 4
#define CT_WH  1024                   // 16 x 1 x 64
#define CT_W2  256                    // 4 x 1 x 64
#define CT_ALL (CT_WG2 + CT_WH + CT_W2)   // 1408

// ---------------- device scratch ----------------
__device__ float g_part[K1_KS * BB * G1D];     // 16 MB
__device__ __nv_bfloat16 g_h1hi[BB * G1D];
__device__ __nv_bfloat16 g_h1lo[BB * G1D];
__device__ __nv_bfloat16 g_wg2thi[PDIM * G1D];
__device__ __nv_bfloat16 g_wg2tlo[PDIM * G1D];
__device__ __nv_bfloat16 g_hhi[BB * PDIM];
__device__ __nv_bfloat16 g_hlo[BB * PDIM];
__device__ __nv_bfloat16 g_whthi[DDIM * HDIM * PDIM];
__device__ __nv_bfloat16 g_whtlo[DDIM * HDIM * PDIM];
__device__ float g_hWh[DDIM * BB * HDIM];
__device__ __nv_bfloat16 g_w2thi[DDIM * HDIM * HDIM];
__device__ __nv_bfloat16 g_w2tlo[DDIM * HDIM * HDIM];
__device__ float g_js[DDIM * 8];
__device__ float g_es[DDIM * 8];

__device__ __forceinline__ float eluf(float x) {
    return x > 0.f ? x : expm1f(x);
}
__device__ __forceinline__ uint32_t smem_u32(const void* p) {
    uint32_t a;
    asm("{ .reg .u64 t; cvta.to.shared.u64 t, %1; cvt.u32.u64 %0, t; }"
        : "=r"(a) : "l"(p));
    return a;
}
#define CP16(dst, src) \
    asm volatile("cp.async.cg.shared.global [%0], [%1], 16;" \
                 :: "r"(dst), "l"(src) : "memory")
#define CP_COMMIT() asm volatile("cp.async.commit_group;" ::: "memory")
#define CP_WAIT1()  asm volatile("cp.async.wait_group 1;" ::: "memory")
#define CP_WAIT0()  asm volatile("cp.async.wait_group 0;" ::: "memory")

__device__ __forceinline__ void ldmx4(uint32_t* r, uint32_t addr) {
    asm volatile("ldmatrix.sync.aligned.m8n8.x4.shared.b16 {%0,%1,%2,%3}, [%4];"
                 : "=r"(r[0]), "=r"(r[1]), "=r"(r[2]), "=r"(r[3]) : "r"(addr));
}
__device__ __forceinline__ void ldmx4t(uint32_t* r, uint32_t addr) {
    asm volatile("ldmatrix.sync.aligned.m8n8.x4.trans.shared.b16 {%0,%1,%2,%3}, [%4];"
                 : "=r"(r[0]), "=r"(r[1]), "=r"(r[2]), "=r"(r[3]) : "r"(addr));
}
__device__ __forceinline__ void mma16816(float* c, const uint32_t* a,
                                         uint32_t b0, uint32_t b1) {
    asm volatile(
        "mma.sync.aligned.m16n8k16.row.col.f32.bf16.bf16.f32 "
        "{%0,%1,%2,%3}, {%4,%5,%6,%7}, {%8,%9}, {%0,%1,%2,%3};"
        : "+f"(c[0]), "+f"(c[1]), "+f"(c[2]), "+f"(c[3])
        : "r"(a[0]), "r"(a[1]), "r"(a[2]), "r"(a[3]), "r"(b0), "r"(b1));
}
__device__ __forceinline__ void hilo(float v, __nv_bfloat16& h, __nv_bfloat16& l) {
    h = __float2bfloat16(v);
    l = __float2bfloat16(v - __bfloat162float(h));
}
// pack 8 fp32 -> 16B hi + 16B lo
__device__ __forceinline__ void pack8(const float* v, uint4& H, uint4& L) {
    uint32_t hw[4], lw[4];
#pragma unroll
    for (int j = 0; j < 4; j++) {
        __nv_bfloat16 h0, l0, h1, l1;
        hilo(v[2 * j], h0, l0);
        hilo(v[2 * j + 1], h1, l1);
        __nv_bfloat162 ph; ph.x = h0; ph.y = h1;
        __nv_bfloat162 pl; pl.x = l0; pl.y = l1;
        hw[j] = *(uint32_t*)&ph;
        lw[j] = *(uint32_t*)&pl;
    }
    H = make_uint4(hw[0], hw[1], hw[2], hw[3]);
    L = make_uint4(lw[0], lw[1], lw[2], lw[3]);
}

// ---------------- merged transpose-convert (all three weights) --------------
// One 32x128 source tile per block; src [R][C] fp32 -> dst [C][R] bf16 hi/lo.
__global__ void __launch_bounds__(256) transconv_all_kernel(
    const float* __restrict__ Wg2, const float* __restrict__ Wh,
    const float* __restrict__ W2)
{
    __shared__ float s[32 * 129];
    const int t = blockIdx.x;
    const int tid = threadIdx.x;

    const float* src;
    __nv_bfloat16 *dhi, *dlo;
    int R, C, zi, rt, ct;
    if (t < CT_WG2) {
        src = Wg2; dhi = g_wg2thi; dlo = g_wg2tlo;
        R = G1D; C = PDIM; zi = 0; rt = t >> 2; ct = t & 3;
    } else if (t < CT_WG2 + CT_WH) {
        int u = t - CT_WG2;
        src = Wh; dhi = g_whthi; dlo = g_whtlo;
        R = PDIM; C = HDIM; zi = u >> 4; rt = u & 15; ct = 0;
    } else {
        int u = t - CT_WG2 - CT_WH;
        src = W2; dhi = g_w2thi; dlo = g_w2tlo;
        R = HDIM; C = HDIM; zi = u >> 2; rt = u & 3; ct = 0;
    }
    const size_t zoff = (size_t)zi * R * C;

    // load 32x128 tile (float4)
#pragma unroll
    for (int i = 0; i < 4; i++) {
        int u = tid + i * 256;
        int r = u >> 5, c4 = u & 31;
        float4 v = __ldg((const float4*)(src + zoff +
                         (size_t)(rt * 32 + r) * C + ct * 128 + c4 * 4));
        s[r * 129 + c4 * 4 + 0] = v.x;
        s[r * 129 + c4 * 4 + 1] = v.y;
        s[r * 129 + c4 * 4 + 2] = v.z;
        s[r * 129 + c4 * 4 + 3] = v.w;
    }
    __syncthreads();

    // transposed convert-store: out[c][r], bf16x2 along r
#pragma unroll
    for (int i = 0; i < 8; i++) {
        int u = tid + i * 256;
        int c = u >> 4, rp = u & 15;
        float a = s[(2 * rp) * 129 + c];
        float b = s[(2 * rp + 1) * 129 + c];
        __nv_bfloat16 ah, al, bh, bl;
        hilo(a, ah, al); hilo(b, bh, bl);
        __nv_bfloat162 vh; vh.x = ah; vh.y = bh;
        __nv_bfloat162 vl; vl.x = al; vl.y = bl;
        size_t o = zoff + (size_t)(ct * 128 + c) * R + rt * 32 + rp * 2;
        *(__nv_bfloat162*)(dhi + o) = vh;
        *(__nv_bfloat162*)(dlo + o) = vl;
    }
}

// ---------------- K1: fused-convert bf16-split HMMA (R9 exact) --------------
__global__ void __launch_bounds__(256, 1) gemm_k1_kernel(
    const float* __restrict__ x, const float* __restrict__ Wg1)
{
    extern __shared__ char sm[];
    const uint32_t sb = smem_u32(sm);
    const int tid = threadIdx.x;
    const int lane = tid & 31;
    const int wid = tid >> 5;
    const int warpM = wid >> 2;   // 0..1 -> 64 rows
    const int warpN = wid & 3;    // 0..3 -> 64 cols

    const int nBase = blockIdx.x * K1_BN;
    const int mBase = blockIdx.y * BM;
    const int kBase = blockIdx.z * K1_KCHUNK;

    const uint32_t laneOffA =
        (uint32_t)(((lane & 7) + ((lane >> 3) & 1) * 8) * ROWB + (lane >> 4) * 16);
    const uint32_t laneOffB =
        (uint32_t)(((lane & 7) + ((lane >> 3) & 1) * 8) * K1_B_PITCH +
                   (lane >> 4) * 16);

    float acc[4][8][4];
#pragma unroll
    for (int i = 0; i < 4; i++)
#pragma unroll
        for (int j = 0; j < 8; j++)
#pragma unroll
            for (int k = 0; k < 4; k++) acc[i][j][k] = 0.f;

    float pfA[2][8], pfB[4][8];

    auto LDG_STAGE = [&](int itn) {
        const int k0 = kBase + itn * BK;
#pragma unroll
        for (int t = 0; t < 2; t++) {
            int u = tid + t * 256;
            int m = u >> 2, kc = (u & 3) * 8;
            const float4* s = (const float4*)(x + (size_t)(mBase + m) * XDIM + k0 + kc);
            float4 v0 = __ldg(s), v1 = __ldg(s + 1);
            pfA[t][0] = v0.x; pfA[t][1] = v0.y; pfA[t][2] = v0.z; pfA[t][3] = v0.w;
            pfA[t][4] = v1.x; pfA[t][5] = v1.y; pfA[t][6] = v1.z; pfA[t][7] = v1.w;
        }
#pragma unroll
        for (int t = 0; t < 4; t++) {
            int u = tid + t * 256;
            int k = u >> 5, n8 = (u & 31) * 8;
            const float4* s = (const float4*)(Wg1 + (size_t)(k0 + k) * G1D + nBase + n8);
            float4 v0 = __ldg(s), v1 = __ldg(s + 1);
            pfB[t][0] = v0.x; pfB[t][1] = v0.y; pfB[t][2] = v0.z; pfB[t][3] = v0.w;
            pfB[t][4] = v1.x; pfB[t][5] = v1.y; pfB[t][6] = v1.z; pfB[t][7] = v1.w;
        }
    };
    auto STS_STAGE = [&](int stage) {
        char* st = sm + (size_t)stage * K1_STG;
#pragma unroll
        for (int t = 0; t < 2; t++) {
            int u = tid + t * 256;
            int m = u >> 2, kc = (u & 3) * 8;
            uint4 H, L;
            pack8(pfA[t], H, L);
            uint32_t so = (uint32_t)(m * ROWB + kc * 2);
            *(uint4*)(st + K1_AH + so) = H;
            *(uint4*)(st + K1_AL + so) = L;
        }
#pragma unroll
        for (int t = 0; t < 4; t++) {
            int u = tid + t * 256;
            int k = u >> 5, n8 = (u & 31) * 8;
            uint4 H, L;
            pack8(pfB[t], H, L);
            uint32_t so = (uint32_t)(k * K1_B_PITCH + n8 * 2);
            *(uint4*)(st + K1_BH + so) = H;
            *(uint4*)(st + K1_BL + so) = L;
        }
    };

    LDG_STAGE(0); STS_STAGE(0);
    LDG_STAGE(1); STS_STAGE(1);
    __syncthreads();

#pragma unroll 1
    for (int it = 0; it < K1_NIT; it++) {
        const bool pf = (it + 2 < K1_NIT);
        if (pf) LDG_STAGE(it + 2);

        uint32_t st = sb + (uint32_t)(it % 3) * K1_STG;
        uint32_t aH = st + K1_AH + (uint32_t)(warpM * 64) * ROWB + laneOffA;
        uint32_t aL = st + K1_AL + (uint32_t)(warpM * 64) * ROWB + laneOffA;
        uint32_t bH = st + K1_BH + (uint32_t)(warpN * 64) * 2 + laneOffB;
        uint32_t bL = st + K1_BL + (uint32_t)(warpN * 64) * 2 + laneOffB;

#pragma unroll
        for (int ks = 0; ks < 2; ks++) {
            const uint32_t kbA = ks * 32;
            const uint32_t kbB = ks * 16 * K1_B_PITCH;
            uint32_t ah[4][4], al[4][4];
#pragma unroll
            for (int mt = 0; mt < 4; mt++) {
                ldmx4(ah[mt], aH + (uint32_t)(mt * 16) * ROWB + kbA);
                ldmx4(al[mt], aL + (uint32_t)(mt * 16) * ROWB + kbA);
            }
#pragma unroll
            for (int p = 0; p < 4; p++) {
                uint32_t bh[4], bl[4];
                ldmx4t(bh, bH + (uint32_t)(p * 32) + kbB);
                ldmx4t(bl, bL + (uint32_t)(p * 32) + kbB);
#pragma unroll
                for (int mt = 0; mt < 4; mt++) {
                    mma16816(acc[mt][2 * p], ah[mt], bh[0], bh[1]);
                    mma16816(acc[mt][2 * p], ah[mt], bl[0], bl[1]);
                    mma16816(acc[mt][2 * p], al[mt], bh[0], bh[1]);
                    mma16816(acc[mt][2 * p + 1], ah[mt], bh[2], bh[3]);
                    mma16816(acc[mt][2 * p + 1], ah[mt], bl[2], bl[3]);
                    mma16816(acc[mt][2 * p + 1], al[mt], bh[2], bh[3]);
                }
            }
        }

        if (pf) STS_STAGE((it + 2) % 3);
        __syncthreads();
    }

    float* base = g_part + (size_t)blockIdx.z * (BB * G1D);
#pragma unroll
    for (int mt = 0; mt < 4; mt++) {
        int m0 = mBase + warpM * 64 + mt * 16 + (lane >> 2);
#pragma unroll
        for (int nt = 0; nt < 8; nt++) {
            int n0 = nBase + warpN * 64 + nt * 8 + (lane & 3) * 2;
            *(float2*)(base + (size_t)m0 * G1D + n0) =
                make_float2(acc[mt][nt][0], acc[mt][nt][1]);
            *(float2*)(base + (size_t)(m0 + 8) * G1D + n0) =
                make_float2(acc[mt][nt][2], acc[mt][nt][3]);
        }
    }
}

// partials -> h1 = elu(sum + bias), bf16 hi/lo (float4)
__global__ void reduce_h1_kernel(const float* __restrict__ bg1) {
    const int i4 = blockIdx.x * 256 + threadIdx.x;
    float4 s = make_float4(0.f, 0.f, 0.f, 0.f);
#pragma unroll
    for (int k = 0; k < K1_KS; k++) {
        float4 v = ((const float4*)g_part)[k * (BB * G1D / 4) + i4];
        s.x += v.x; s.y += v.y; s.z += v.z; s.w += v.w;
    }
    const int c0 = (i4 * 4) & (G1D - 1);
    float4 b = *(const float4*)(bg1 + c0);
    float u0 = eluf(s.x + b.x), u1 = eluf(s.y + b.y);
    float u2 = eluf(s.z + b.z), u3 = eluf(s.w + b.w);
    __nv_bfloat16 h0, h1, h2, h3, l0, l1, l2, l3;
    hilo(u0, h0, l0); hilo(u1, h1, l1); hilo(u2, h2, l2); hilo(u3, h3, l3);
    __nv_bfloat162 vh0, vh1, vl0, vl1;
    vh0.x = h0; vh0.y = h1; vh1.x = h2; vh1.y = h3;
    vl0.x = l0; vl0.y = l1; vl1.x = l2; vl1.y = l3;
    ((__nv_bfloat162*)g_h1hi)[2 * i4] = vh0;
    ((__nv_bfloat162*)g_h1hi)[2 * i4 + 1] = vh1;
    ((__nv_bfloat162*)g_h1lo)[2 * i4] = vl0;
    ((__nv_bfloat162*)g_h1lo)[2 * i4 + 1] = vl1;
}

// ---------------- unified bf16-split HMMA GEMM (BN=128) ----------------
template <int EPI>
__global__ void __launch_bounds__(256, 2) gemm_bs(
    const __nv_bfloat16* __restrict__ Ahi, const __nv_bfloat16* __restrict__ Alo,
    int lda, long sAz,
    const __nv_bfloat16* __restrict__ Bhi, const __nv_bfloat16* __restrict__ Blo,
    int ldb, long sBz,
    float* __restrict__ C, __nv_bfloat16* __restrict__ Chi,
    __nv_bfloat16* __restrict__ Clo,
    const float* __restrict__ bias, int ldc, long sCz, int K,
    const float* __restrict__ b2, const float* __restrict__ W3,
    const float* __restrict__ b3,
    const float* __restrict__ hwhp, const float* __restrict__ zv,
    const int* __restrict__ permp, const float* __restrict__ Wzp,
    const float* __restrict__ b1p)
{
    extern __shared__ char sm[];
    __shared__ float red[128][5];
    __shared__ float wr[8];
    __shared__ float s_wz[HDIM], s_b1[HDIM];
    const uint32_t sb = smem_u32(sm);
    const int tid = threadIdx.x;
    const int lane = tid & 31;
    const int wid = tid >> 5;
    const int warpM = wid >> 2;
    const int warpN = wid & 3;

    const int nBase = blockIdx.x * 128;
    const int mBase = blockIdx.y * BM;
    const __nv_bfloat16* ahiz = Ahi + (size_t)blockIdx.z * sAz;
    const __nv_bfloat16* aloz = Alo + (size_t)blockIdx.z * sAz;
    const __nv_bfloat16* bhi = Bhi + (size_t)blockIdx.z * sBz;
    const __nv_bfloat16* blo = Blo + (size_t)blockIdx.z * sBz;

    if (EPI == 2) {
        if (tid < HDIM) {
            s_wz[tid] = Wzp[(size_t)blockIdx.z * HDIM + tid];
            s_b1[tid] = b1p[(size_t)blockIdx.z * HDIM + tid];
        }
        __syncthreads();
    }

    const uint32_t laneOff =
        (uint32_t)(((lane & 7) + ((lane >> 3) & 1) * 8) * ROWB + (lane >> 4) * 16);
    const int NIT = K / BK;

    float acc[4][4][4];
#pragma unroll
    for (int i = 0; i < 4; i++)
#pragma unroll
        for (int j = 0; j < 4; j++)
#pragma unroll
            for (int k = 0; k < 4; k++) acc[i][j][k] = 0.f;

#define A_COMPUTE(stage, k0)                                                   \
    do {                                                                       \
        uint32_t stoff = (uint32_t)(stage) * STG_BYTES;                        \
        const float* hwh_d = hwhp + (size_t)blockIdx.z * BB * HDIM;            \
        _Pragma("unroll")                                                      \
        for (int t = 0; t < 2; t++) {                                          \
            int u = tid + t * 256;                                             \
            int r = u >> 2, ch = u & 3;                                        \
            int gm = mBase + r;                                                \
            int b = (gm < BB) ? gm : gm - BB;                                  \
            int src = (gm < BB) ? b : __ldg(permp + b);                        \
            float zb = __ldg(zv + (size_t)b * DDIM + blockIdx.z);              \
            const float* hr = hwh_d + (size_t)src * HDIM + (k0) + ch * 8;      \
            float4 v0 = __ldg((const float4*)hr);                              \
            float4 v1 = __ldg((const float4*)(hr + 4));                        \
            float hv[8] = {v0.x, v0.y, v0.z, v0.w, v1.x, v1.y, v1.z, v1.w};    \
            uint32_t hp[4], lp[4];                                             \
            _Pragma("unroll")                                                  \
            for (int j = 0; j < 4; j++) {                                      \
                int kk = (k0) + ch * 8 + 2 * j;                                \
                float a0 = eluf(hv[2*j]   + fmaf(zb, s_wz[kk],   s_b1[kk]));   \
                float a1v = eluf(hv[2*j+1] + fmaf(zb, s_wz[kk+1], s_b1[kk+1]));\
                __nv_bfloat16 hh0, ll0, hh1, ll1;                              \
                hilo(a0, hh0, ll0); hilo(a1v, hh1, ll1);                       \
                __nv_bfloat162 ph; ph.x = hh0; ph.y = hh1;                     \
                __nv_bfloat162 pl; pl.x = ll0; pl.y = ll1;                     \
                hp[j] = *(uint32_t*)&ph; lp[j] = *(uint32_t*)&pl;              \
            }                                                                  \
            uint32_t so = (uint32_t)(r * ROWB + ch * 16);                      \
            *(uint4*)(sm + stoff + 0 * MAT_BYTES + so) =                       \
                make_uint4(hp[0], hp[1], hp[2], hp[3]);                        \
            *(uint4*)(sm + stoff + 1 * MAT_BYTES + so) =                       \
                make_uint4(lp[0], lp[1], lp[2], lp[3]);                        \
        }                                                                      \
    } while (0)

#define BS_LOAD(stage, k0)                                                     \
    do {                                                                       \
        uint32_t st = sb + (uint32_t)(stage)*STG_BYTES;                        \
        if (EPI == 2) {                                                        \
            A_COMPUTE(stage, k0);                                              \
        } else {                                                               \
            _Pragma("unroll")                                                  \
            for (int t = 0; t < 2; t++) {                                      \
                int ci = tid + t * 256;                                        \
                int r = ci >> 2, ch = ci & 3;                                  \
                uint32_t so = (uint32_t)(r * ROWB + ch * 16);                  \
                size_t goA = (size_t)(mBase + r) * lda + (k0) + ch * 8;        \
                CP16(st + 0 * MAT_BYTES + so, ahiz + goA);                     \
                CP16(st + 1 * MAT_BYTES + so, aloz + goA);                     \
            }                                                                  \
        }                                                                      \
        _Pragma("unroll")                                                      \
        for (int t = 0; t < 2; t++) {                                          \
            int ci = tid + t * 256;                                            \
            int r = ci >> 2, ch = ci & 3;                                      \
            uint32_t so = (uint32_t)(r * ROWB + ch * 16);                      \
            size_t goB = (size_t)(nBase + r) * ldb + (k0) + ch * 8;            \
            CP16(st + 2 * MAT_BYTES + so, bhi + goB);                          \
            CP16(st + 3 * MAT_BYTES + so, blo + goB);                          \
        }                                                                      \
    } while (0)

    BS_LOAD(0, 0);
    CP_COMMIT();

#pragma unroll 1
    for (int it = 0; it < NIT; it++) {
        if (it + 1 < NIT) {
            BS_LOAD((it + 1) & 1, (it + 1) * BK);
            CP_COMMIT();
            CP_WAIT1();
        } else {
            CP_WAIT0();
        }
        __syncthreads();

        uint32_t st = sb + (uint32_t)(it & 1) * STG_BYTES;
        uint32_t aH = st + 0 * MAT_BYTES + (uint32_t)(warpM * 64) * ROWB + laneOff;
        uint32_t aL = st + 1 * MAT_BYTES + (uint32_t)(warpM * 64) * ROWB + laneOff;
        uint32_t bH = st + 2 * MAT_BYTES + (uint32_t)(warpN * 32) * ROWB + laneOff;
        uint32_t bL = st + 3 * MAT_BYTES + (uint32_t)(warpN * 32) * ROWB + laneOff;

#pragma unroll
        for (int ks = 0; ks < 2; ks++) {
            const uint32_t kb = ks * 32;
            uint32_t ah[4][4], al[4][4], bh[2][4], bl[2][4];
#pragma unroll
            for (int mt = 0; mt < 4; mt++) {
                ldmx4(ah[mt], aH + (uint32_t)(mt * 16) * ROWB + kb);
                ldmx4(al[mt], aL + (uint32_t)(mt * 16) * ROWB + kb);
            }
#pragma unroll
            for (int p = 0; p < 2; p++) {
                ldmx4(bh[p], bH + (uint32_t)(p * 16) * ROWB + kb);
                ldmx4(bl[p], bL + (uint32_t)(p * 16) * ROWB + kb);
            }
#pragma unroll
            for (int mt = 0; mt < 4; mt++) {
#pragma unroll
                for (int nt = 0; nt < 4; nt++) {
                    const int p = nt >> 1, q = nt & 1;
                    mma16816(acc[mt][nt], ah[mt], bh[p][q], bh[p][q + 2]);
                    mma16816(acc[mt][nt], ah[mt], bl[p][q], bl[p][q + 2]);
                    mma16816(acc[mt][nt], al[mt], bh[p][q], bh[p][q + 2]);
                }
            }
        }
        __syncthreads();
    }
#undef BS_LOAD
#undef A_COMPUTE

    if (EPI == 2) {
        const float* b2z = b2 + (size_t)blockIdx.z * HDIM;
        const float* w3z = W3 + (size_t)blockIdx.z * HDIM;
        const float b3d = b3[blockIdx.z];
        const bool joint = (blockIdx.y < 4);
#pragma unroll
        for (int mt = 0; mt < 4; mt++) {
            float s0 = 0.f, s1 = 0.f;
#pragma unroll
            for (int nt = 0; nt < 4; nt++) {
                int n0 = warpN * 32 + nt * 8 + (lane & 3) * 2;
                float w0 = __ldg(w3z + n0), w1 = __ldg(w3z + n0 + 1);
                float c0 = __ldg(b2z + n0), c1 = __ldg(b2z + n0 + 1);
                s0 += eluf(acc[mt][nt][0] + c0) * w0 + eluf(acc[mt][nt][1] + c1) * w1;
                s1 += eluf(acc[mt][nt][2] + c0) * w0 + eluf(acc[mt][nt][3] + c1) * w1;
            }
            s0 += __shfl_xor_sync(0xffffffffu, s0, 1);
            s0 += __shfl_xor_sync(0xffffffffu, s0, 2);
            s1 += __shfl_xor_sync(0xffffffffu, s1, 1);
            s1 += __shfl_xor_sync(0xffffffffu, s1, 2);
            if ((lane & 3) == 0) {
                int r0 = warpM * 64 + mt * 16 + (lane >> 2);
                red[r0][warpN] = s0;
                red[r0 + 8][warpN] = s1;
            }
        }
        __syncthreads();
        float val = 0.f;
        if (tid < 128) {
            float s = red[tid][0] + red[tid][1] + red[tid][2] + red[tid][3] + b3d;
            val = joint ? s : expf(s);
        }
#pragma unroll
        for (int off = 16; off; off >>= 1)
            val += __shfl_xor_sync(0xffffffffu, val, off);
        if (lane == 0) wr[wid] = val;
        __syncthreads();
        if (tid == 0) {
            float s = wr[0] + wr[1] + wr[2] + wr[3];
            int slot = blockIdx.z * 8 + blockIdx.y;
            if (joint) { g_js[slot] = s; g_es[slot] = 0.f; }
            else       { g_js[slot] = 0.f; g_es[slot] = s; }
        }
        return;
    }

#pragma unroll
    for (int mt = 0; mt < 4; mt++) {
        int m0 = mBase + warpM * 64 + mt * 16 + (lane >> 2);
#pragma unroll
        for (int nt = 0; nt < 4; nt++) {
            int n0 = nBase + warpN * 32 + nt * 8 + (lane & 3) * 2;
            if (EPI == 0) {
                float* Cz = C + (size_t)blockIdx.z * sCz;
                *(float2*)(Cz + (size_t)m0 * ldc + n0) =
                    make_float2(acc[mt][nt][0], acc[mt][nt][1]);
                *(float2*)(Cz + (size_t)(m0 + 8) * ldc + n0) =
                    make_float2(acc[mt][nt][2], acc[mt][nt][3]);
            } else if (EPI == 1) {
                float bv0 = bias[n0], bv1 = bias[n0 + 1];
                float u0 = eluf(acc[mt][nt][0] + bv0);
                float u1 = eluf(acc[mt][nt][1] + bv1);
                float u2 = eluf(acc[mt][nt][2] + bv0);
                float u3 = eluf(acc[mt][nt][3] + bv1);
                __nv_bfloat16 h0, h1, h2, h3, l0, l1, l2, l3;
                hilo(u0, h0, l0); hilo(u1, h1, l1);
                hilo(u2, h2, l2); hilo(u3, h3, l3);
                __nv_bfloat162 vh, vl;
                vh.x = h0; vh.y = h1; vl.x = l0; vl.y = l1;
                *(__nv_bfloat162*)(Chi + (size_t)m0 * ldc + n0) = vh;
                *(__nv_bfloat162*)(Clo + (size_t)m0 * ldc + n0) = vl;
                vh.x = h2; vh.y = h3; vl.x = l2; vl.y = l3;
                *(__nv_bfloat162*)(Chi + (size_t)(m0 + 8) * ldc + n0) = vh;
                *(__nv_bfloat162*)(Clo + (size_t)(m0 + 8) * ldc + n0) = vl;
            }
        }
    }
}

__global__ void finalize_kernel(float* __restrict__ out)
{
    int t = threadIdx.x;
    float acc = 0.f;
    for (int d = t; d < DDIM; d += 32) {
        float js = 0.f, es = 0.f;
#pragma unroll
        for (int c = 0; c < 8; c++) { js += g_js[d * 8 + c]; es += g_es[d * 8 + c]; }
        acc += js * (1.f / BB) - logf(es * (1.f / BB));
    }
#pragma unroll
    for (int off = 16; off; off >>= 1)
        acc += __shfl_xor_sync(0xffffffffu, acc, off);
    if (t == 0) out[0] = -acc * (1.f / DDIM);
}

// ---------------------------------------------------------------------------
extern "C" void kernel_launch(void* const* d_in, const int* in_sizes, int n_in,
                              void* d_out, int out_size)
{
    const float* x   = (const float*)d_in[0];
    const float* z   = (const float*)d_in[1];
    const int*   perm= (const int*)  d_in[2];
    const float* Wg1 = (const float*)d_in[3];
    const float* bg1 = (const float*)d_in[4];
    const float* Wg2 = (const float*)d_in[5];
    const float* bg2 = (const float*)d_in[6];
    const float* Wh  = (const float*)d_in[7];
    const float* Wz  = (const float*)d_in[8];
    const float* b1  = (const float*)d_in[9];
    const float* W2  = (const float*)d_in[10];
    const float* b2  = (const float*)d_in[11];
    const float* W3  = (const float*)d_in[12];
    const float* b3  = (const float*)d_in[13];

    __nv_bfloat16 *h1hi, *h1lo, *wg2thi, *wg2tlo, *hhi, *hlo, *whthi, *whtlo;
    __nv_bfloat16 *w2thi, *w2tlo;
    float* hwh;
    cudaGetSymbolAddress((void**)&h1hi,   g_h1hi);
    cudaGetSymbolAddress((void**)&h1lo,   g_h1lo);
    cudaGetSymbolAddress((void**)&wg2thi, g_wg2thi);
    cudaGetSymbolAddress((void**)&wg2tlo, g_wg2tlo);
    cudaGetSymbolAddress((void**)&hhi,    g_hhi);
    cudaGetSymbolAddress((void**)&hlo,    g_hlo);
    cudaGetSymbolAddress((void**)&whthi,  g_whthi);
    cudaGetSymbolAddress((void**)&whtlo,  g_whtlo);
    cudaGetSymbolAddress((void**)&w2thi,  g_w2thi);
    cudaGetSymbolAddress((void**)&w2tlo,  g_w2tlo);
    cudaGetSymbolAddress((void**)&hwh,    g_hWh);

    // merged weight conversion (single launch)
    transconv_all_kernel<<<CT_ALL, 256>>>(Wg2, Wh, W2);

    // K1: fused fp32->hi/lo loader + bf16-split HMMA (R9 exact)
    cudaFuncSetAttribute(gemm_k1_kernel,
                         cudaFuncAttributeMaxDynamicSharedMemorySize, K1_SMEM);
    gemm_k1_kernel<<<dim3(G1D / K1_BN, BB / BM, K1_KS), 256, K1_SMEM>>>(x, Wg1);
    reduce_h1_kernel<<<(BB * G1D) / 4 / 256, 256>>>(bg1);

    cudaFuncSetAttribute(gemm_bs<0>,
                         cudaFuncAttributeMaxDynamicSharedMemorySize, GEMM_SMEM);
    cudaFuncSetAttribute(gemm_bs<1>,
                         cudaFuncAttributeMaxDynamicSharedMemorySize, GEMM_SMEM);
    cudaFuncSetAttribute(gemm_bs<2>,
                         cudaFuncAttributeMaxDynamicSharedMemorySize, GEMM_SMEM);

    // K2: h = elu(h1 @ Wg2 + bg2) -> bf16 hi/lo
    gemm_bs<1><<<dim3(PDIM / 128, BB / BM, 1), 256, GEMM_SMEM>>>(
        h1hi, h1lo, G1D, 0, wg2thi, wg2tlo, G1D, 0,
        nullptr, hhi, hlo, bg2, PDIM, 0, G1D,
        nullptr, nullptr, nullptr, nullptr, nullptr, nullptr, nullptr, nullptr);

    // K3: hWh[d] = h @ WhT[d]  (fp32)
    gemm_bs<0><<<dim3(1, BB / BM, DDIM), 256, GEMM_SMEM>>>(
        hhi, hlo, PDIM, 0, whthi, whtlo, PDIM, (long)HDIM * PDIM,
        hwh, nullptr, nullptr, nullptr, HDIM, (long)BB * HDIM, PDIM,
        nullptr, nullptr, nullptr, nullptr, nullptr, nullptr, nullptr, nullptr);

    // head: fused a1 compute + a2 GEMM + scores + reductions
    gemm_bs<2><<<dim3(1, (2 * BB) / BM, DDIM), 256, GEMM_SMEM>>>(
        nullptr, nullptr, HDIM, 0,
        w2thi, w2tlo, HDIM, (long)HDIM * HDIM,
        nullptr, nullptr, nullptr, nullptr, HDIM, 0, HDIM,
        b2, W3, b3, hwh, z, perm, Wz, b1);

    finalize_kernel<<<1, 32>>>((float*)d_out);
}

// round 17
// speedup vs baseline: 2.0723x; 1.0911x over previous
#include <cuda_runtime.h>
#include <cuda_bf16.h>
#include <math.h>
#include <stdint.h>

// Problem dims
#define BB   512
#define XDIM 32768
#define PDIM 512
#define DDIM 64
#define HDIM 128
#define G1D  1024

// Shared HMMA config
#define BM 128
#define BK 32
#define PITCH 40
#define ROWB (PITCH * 2)        // 80

// gemm_bs (BN=128)
#define MAT_BYTES (128 * ROWB)        // 10240
#define STG_BYTES (4 * MAT_BYTES)     // 40960
#define GEMM_SMEM (2 * STG_BYTES)     // 81920

// K1 (BM=128, BN=256, KS=8, 3-stage, fused fp32->hi/lo loader)  — R9 config
#define K1_BN 256
#define K1_KS 8
#define K1_KCHUNK (XDIM / K1_KS)      // 4096
#define K1_NIT (K1_KCHUNK / BK)       // 128
#define K1_MAT_A 10240                // 128 rows x 80B
#define K1_B_PITCH 528                // 256 n x 2B + 16B pad
#define K1_MAT_B (32 * K1_B_PITCH)    // 16896
#define K1_AH 0
#define K1_AL K1_MAT_A
#define K1_BH (2 * K1_MAT_A)
#define K1_BL (2 * K1_MAT_A + K1_MAT_B)
#define K1_STG (2 * K1_MAT_A + 2 * K1_MAT_B)   // 54272
#define K1_SMEM (3 * K1_STG)                   // 162816

// K2 k-split
#define K2_KS 4
#define K2_KCHUNK (G1D / K2_KS)       // 256

// merged conversion tiles (32 rows x 128 cols each)
#define CT_WG2 128                    // 32 x 4
#define CT_WH  1024                   // 16 x 1 x 64
#define CT_W2  256                    // 4 x 1 x 64
#define CT_ALL (CT_WG2 + CT_WH + CT_W2)   // 1408

// ---------------- device scratch ----------------
__device__ float g_part[K1_KS * BB * G1D];     // 16 MB (reused by K2 partials)
__device__ __nv_bfloat16 g_h1hi[BB * G1D];
__device__ __nv_bfloat16 g_h1lo[BB * G1D];
__device__ __nv_bfloat16 g_wg2thi[PDIM * G1D];
__device__ __nv_bfloat16 g_wg2tlo[PDIM * G1D];
__device__ __nv_bfloat16 g_hhi[BB * PDIM];
__device__ __nv_bfloat16 g_hlo[BB * PDIM];
__device__ __nv_bfloat16 g_whthi[DDIM * HDIM * PDIM];
__device__ __nv_bfloat16 g_whtlo[DDIM * HDIM * PDIM];
__device__ float g_hWh[DDIM * BB * HDIM];
__device__ __nv_bfloat16 g_w2thi[DDIM * HDIM * HDIM];
__device__ __nv_bfloat16 g_w2tlo[DDIM * HDIM * HDIM];
__device__ float g_js[DDIM * 8];
__device__ float g_es[DDIM * 8];

__device__ __forceinline__ float eluf(float x) {
    return x > 0.f ? x : expm1f(x);
}
__device__ __forceinline__ uint32_t smem_u32(const void* p) {
    uint32_t a;
    asm("{ .reg .u64 t; cvta.to.shared.u64 t, %1; cvt.u32.u64 %0, t; }"
        : "=r"(a) : "l"(p));
    return a;
}
#define CP16(dst, src) \
    asm volatile("cp.async.cg.shared.global [%0], [%1], 16;" \
                 :: "r"(dst), "l"(src) : "memory")
#define CP_COMMIT() asm volatile("cp.async.commit_group;" ::: "memory")
#define CP_WAIT1()  asm volatile("cp.async.wait_group 1;" ::: "memory")
#define CP_WAIT0()  asm volatile("cp.async.wait_group 0;" ::: "memory")

__device__ __forceinline__ void ldmx4(uint32_t* r, uint32_t addr) {
    asm volatile("ldmatrix.sync.aligned.m8n8.x4.shared.b16 {%0,%1,%2,%3}, [%4];"
                 : "=r"(r[0]), "=r"(r[1]), "=r"(r[2]), "=r"(r[3]) : "r"(addr));
}
__device__ __forceinline__ void ldmx4t(uint32_t* r, uint32_t addr) {
    asm volatile("ldmatrix.sync.aligned.m8n8.x4.trans.shared.b16 {%0,%1,%2,%3}, [%4];"
                 : "=r"(r[0]), "=r"(r[1]), "=r"(r[2]), "=r"(r[3]) : "r"(addr));
}
__device__ __forceinline__ void mma16816(float* c, const uint32_t* a,
                                         uint32_t b0, uint32_t b1) {
    asm volatile(
        "mma.sync.aligned.m16n8k16.row.col.f32.bf16.bf16.f32 "
        "{%0,%1,%2,%3}, {%4,%5,%6,%7}, {%8,%9}, {%0,%1,%2,%3};"
        : "+f"(c[0]), "+f"(c[1]), "+f"(c[2]), "+f"(c[3])
        : "r"(a[0]), "r"(a[1]), "r"(a[2]), "r"(a[3]), "r"(b0), "r"(b1));
}
__device__ __forceinline__ void hilo(float v, __nv_bfloat16& h, __nv_bfloat16& l) {
    h = __float2bfloat16(v);
    l = __float2bfloat16(v - __bfloat162float(h));
}
// pack 8 fp32 -> 16B hi + 16B lo
__device__ __forceinline__ void pack8(const float* v, uint4& H, uint4& L) {
    uint32_t hw[4], lw[4];
#pragma unroll
    for (int j = 0; j < 4; j++) {
        __nv_bfloat16 h0, l0, h1, l1;
        hilo(v[2 * j], h0, l0);
        hilo(v[2 * j + 1], h1, l1);
        __nv_bfloat162 ph; ph.x = h0; ph.y = h1;
        __nv_bfloat162 pl; pl.x = l0; pl.y = l1;
        hw[j] = *(uint32_t*)&ph;
        lw[j] = *(uint32_t*)&pl;
    }
    H = make_uint4(hw[0], hw[1], hw[2], hw[3]);
    L = make_uint4(lw[0], lw[1], lw[2], lw[3]);
}

// ---------------- merged transpose-convert (all three weights) --------------
__global__ void __launch_bounds__(256) transconv_all_kernel(
    const float* __restrict__ Wg2, const float* __restrict__ Wh,
    const float* __restrict__ W2)
{
    __shared__ float s[32 * 129];
    const int t = blockIdx.x;
    const int tid = threadIdx.x;

    const float* src;
    __nv_bfloat16 *dhi, *dlo;
    int R, C, zi, rt, ct;
    if (t < CT_WG2) {
        src = Wg2; dhi = g_wg2thi; dlo = g_wg2tlo;
        R = G1D; C = PDIM; zi = 0; rt = t >> 2; ct = t & 3;
    } else if (t < CT_WG2 + CT_WH) {
        int u = t - CT_WG2;
        src = Wh; dhi = g_whthi; dlo = g_whtlo;
        R = PDIM; C = HDIM; zi = u >> 4; rt = u & 15; ct = 0;
    } else {
        int u = t - CT_WG2 - CT_WH;
        src = W2; dhi = g_w2thi; dlo = g_w2tlo;
        R = HDIM; C = HDIM; zi = u >> 2; rt = u & 3; ct = 0;
    }
    const size_t zoff = (size_t)zi * R * C;

#pragma unroll
    for (int i = 0; i < 4; i++) {
        int u = tid + i * 256;
        int r = u >> 5, c4 = u & 31;
        float4 v = __ldg((const float4*)(src + zoff +
                         (size_t)(rt * 32 + r) * C + ct * 128 + c4 * 4));
        s[r * 129 + c4 * 4 + 0] = v.x;
        s[r * 129 + c4 * 4 + 1] = v.y;
        s[r * 129 + c4 * 4 + 2] = v.z;
        s[r * 129 + c4 * 4 + 3] = v.w;
    }
    __syncthreads();

#pragma unroll
    for (int i = 0; i < 8; i++) {
        int u = tid + i * 256;
        int c = u >> 4, rp = u & 15;
        float a = s[(2 * rp) * 129 + c];
        float b = s[(2 * rp + 1) * 129 + c];
        __nv_bfloat16 ah, al, bh, bl;
        hilo(a, ah, al); hilo(b, bh, bl);
        __nv_bfloat162 vh; vh.x = ah; vh.y = bh;
        __nv_bfloat162 vl; vl.x = al; vl.y = bl;
        size_t o = zoff + (size_t)(ct * 128 + c) * R + rt * 32 + rp * 2;
        *(__nv_bfloat162*)(dhi + o) = vh;
        *(__nv_bfloat162*)(dlo + o) = vl;
    }
}

// ---------------- K1: fused-convert bf16-split HMMA (R9 exact) --------------
__global__ void __launch_bounds__(256, 1) gemm_k1_kernel(
    const float* __restrict__ x, const float* __restrict__ Wg1)
{
    extern __shared__ char sm[];
    const uint32_t sb = smem_u32(sm);
    const int tid = threadIdx.x;
    const int lane = tid & 31;
    const int wid = tid >> 5;
    const int warpM = wid >> 2;
    const int warpN = wid & 3;

    const int nBase = blockIdx.x * K1_BN;
    const int mBase = blockIdx.y * BM;
    const int kBase = blockIdx.z * K1_KCHUNK;

    const uint32_t laneOffA =
        (uint32_t)(((lane & 7) + ((lane >> 3) & 1) * 8) * ROWB + (lane >> 4) * 16);
    const uint32_t laneOffB =
        (uint32_t)(((lane & 7) + ((lane >> 3) & 1) * 8) * K1_B_PITCH +
                   (lane >> 4) * 16);

    float acc[4][8][4];
#pragma unroll
    for (int i = 0; i < 4; i++)
#pragma unroll
        for (int j = 0; j < 8; j++)
#pragma unroll
            for (int k = 0; k < 4; k++) acc[i][j][k] = 0.f;

    float pfA[2][8], pfB[4][8];

    auto LDG_STAGE = [&](int itn) {
        const int k0 = kBase + itn * BK;
#pragma unroll
        for (int t = 0; t < 2; t++) {
            int u = tid + t * 256;
            int m = u >> 2, kc = (u & 3) * 8;
            const float4* s = (const float4*)(x + (size_t)(mBase + m) * XDIM + k0 + kc);
            float4 v0 = __ldg(s), v1 = __ldg(s + 1);
            pfA[t][0] = v0.x; pfA[t][1] = v0.y; pfA[t][2] = v0.z; pfA[t][3] = v0.w;
            pfA[t][4] = v1.x; pfA[t][5] = v1.y; pfA[t][6] = v1.z; pfA[t][7] = v1.w;
        }
#pragma unroll
        for (int t = 0; t < 4; t++) {
            int u = tid + t * 256;
            int k = u >> 5, n8 = (u & 31) * 8;
            const float4* s = (const float4*)(Wg1 + (size_t)(k0 + k) * G1D + nBase + n8);
            float4 v0 = __ldg(s), v1 = __ldg(s + 1);
            pfB[t][0] = v0.x; pfB[t][1] = v0.y; pfB[t][2] = v0.z; pfB[t][3] = v0.w;
            pfB[t][4] = v1.x; pfB[t][5] = v1.y; pfB[t][6] = v1.z; pfB[t][7] = v1.w;
        }
    };
    auto STS_STAGE = [&](int stage) {
        char* st = sm + (size_t)stage * K1_STG;
#pragma unroll
        for (int t = 0; t < 2; t++) {
            int u = tid + t * 256;
            int m = u >> 2, kc = (u & 3) * 8;
            uint4 H, L;
            pack8(pfA[t], H, L);
            uint32_t so = (uint32_t)(m * ROWB + kc * 2);
            *(uint4*)(st + K1_AH + so) = H;
            *(uint4*)(st + K1_AL + so) = L;
        }
#pragma unroll
        for (int t = 0; t < 4; t++) {
            int u = tid + t * 256;
            int k = u >> 5, n8 = (u & 31) * 8;
            uint4 H, L;
            pack8(pfB[t], H, L);
            uint32_t so = (uint32_t)(k * K1_B_PITCH + n8 * 2);
            *(uint4*)(st + K1_BH + so) = H;
            *(uint4*)(st + K1_BL + so) = L;
        }
    };

    LDG_STAGE(0); STS_STAGE(0);
    LDG_STAGE(1); STS_STAGE(1);
    __syncthreads();

#pragma unroll 1
    for (int it = 0; it < K1_NIT; it++) {
        const bool pf = (it + 2 < K1_NIT);
        if (pf) LDG_STAGE(it + 2);

        uint32_t st = sb + (uint32_t)(it % 3) * K1_STG;
        uint32_t aH = st + K1_AH + (uint32_t)(warpM * 64) * ROWB + laneOffA;
        uint32_t aL = st + K1_AL + (uint32_t)(warpM * 64) * ROWB + laneOffA;
        uint32_t bH = st + K1_BH + (uint32_t)(warpN * 64) * 2 + laneOffB;
        uint32_t bL = st + K1_BL + (uint32_t)(warpN * 64) * 2 + laneOffB;

#pragma unroll
        for (int ks = 0; ks < 2; ks++) {
            const uint32_t kbA = ks * 32;
            const uint32_t kbB = ks * 16 * K1_B_PITCH;
            uint32_t ah[4][4], al[4][4];
#pragma unroll
            for (int mt = 0; mt < 4; mt++) {
                ldmx4(ah[mt], aH + (uint32_t)(mt * 16) * ROWB + kbA);
                ldmx4(al[mt], aL + (uint32_t)(mt * 16) * ROWB + kbA);
            }
#pragma unroll
            for (int p = 0; p < 4; p++) {
                uint32_t bh[4], bl[4];
                ldmx4t(bh, bH + (uint32_t)(p * 32) + kbB);
                ldmx4t(bl, bL + (uint32_t)(p * 32) + kbB);
#pragma unroll
                for (int mt = 0; mt < 4; mt++) {
                    mma16816(acc[mt][2 * p], ah[mt], bh[0], bh[1]);
                    mma16816(acc[mt][2 * p], ah[mt], bl[0], bl[1]);
                    mma16816(acc[mt][2 * p], al[mt], bh[0], bh[1]);
                    mma16816(acc[mt][2 * p + 1], ah[mt], bh[2], bh[3]);
                    mma16816(acc[mt][2 * p + 1], ah[mt], bl[2], bl[3]);
                    mma16816(acc[mt][2 * p + 1], al[mt], bh[2], bh[3]);
                }
            }
        }

        if (pf) STS_STAGE((it + 2) % 3);
        __syncthreads();
    }

    float* base = g_part + (size_t)blockIdx.z * (BB * G1D);
#pragma unroll
    for (int mt = 0; mt < 4; mt++) {
        int m0 = mBase + warpM * 64 + mt * 16 + (lane >> 2);
#pragma unroll
        for (int nt = 0; nt < 8; nt++) {
            int n0 = nBase + warpN * 64 + nt * 8 + (lane & 3) * 2;
            *(float2*)(base + (size_t)m0 * G1D + n0) =
                make_float2(acc[mt][nt][0], acc[mt][nt][1]);
            *(float2*)(base + (size_t)(m0 + 8) * G1D + n0) =
                make_float2(acc[mt][nt][2], acc[mt][nt][3]);
        }
    }
}

// partials -> h1 = elu(sum + bias), bf16 hi/lo (float4)
__global__ void reduce_h1_kernel(const float* __restrict__ bg1) {
    const int i4 = blockIdx.x * 256 + threadIdx.x;
    float4 s = make_float4(0.f, 0.f, 0.f, 0.f);
#pragma unroll
    for (int k = 0; k < K1_KS; k++) {
        float4 v = ((const float4*)g_part)[k * (BB * G1D / 4) + i4];
        s.x += v.x; s.y += v.y; s.z += v.z; s.w += v.w;
    }
    const int c0 = (i4 * 4) & (G1D - 1);
    float4 b = *(const float4*)(bg1 + c0);
    float u0 = eluf(s.x + b.x), u1 = eluf(s.y + b.y);
    float u2 = eluf(s.z + b.z), u3 = eluf(s.w + b.w);
    __nv_bfloat16 h0, h1, h2, h3, l0, l1, l2, l3;
    hilo(u0, h0, l0); hilo(u1, h1, l1); hilo(u2, h2, l2); hilo(u3, h3, l3);
    __nv_bfloat162 vh0, vh1, vl0, vl1;
    vh0.x = h0; vh0.y = h1; vh1.x = h2; vh1.y = h3;
    vl0.x = l0; vl0.y = l1; vl1.x = l2; vl1.y = l3;
    ((__nv_bfloat162*)g_h1hi)[2 * i4] = vh0;
    ((__nv_bfloat162*)g_h1hi)[2 * i4 + 1] = vh1;
    ((__nv_bfloat162*)g_h1lo)[2 * i4] = vl0;
    ((__nv_bfloat162*)g_h1lo)[2 * i4 + 1] = vl1;
}

// K2 partials -> h = elu(sum + bg2), bf16 hi/lo (float4 over BB*PDIM)
__global__ void reduce_h2_kernel(const float* __restrict__ bg2) {
    const int i4 = blockIdx.x * 256 + threadIdx.x;
    float4 s = make_float4(0.f, 0.f, 0.f, 0.f);
#pragma unroll
    for (int k = 0; k < K2_KS; k++) {
        float4 v = ((const float4*)g_part)[k * (BB * PDIM / 4) + i4];
        s.x += v.x; s.y += v.y; s.z += v.z; s.w += v.w;
    }
    const int c0 = (i4 * 4) & (PDIM - 1);
    float4 b = *(const float4*)(bg2 + c0);
    float u0 = eluf(s.x + b.x), u1 = eluf(s.y + b.y);
    float u2 = eluf(s.z + b.z), u3 = eluf(s.w + b.w);
    __nv_bfloat16 h0, h1, h2, h3, l0, l1, l2, l3;
    hilo(u0, h0, l0); hilo(u1, h1, l1); hilo(u2, h2, l2); hilo(u3, h3, l3);
    __nv_bfloat162 vh0, vh1, vl0, vl1;
    vh0.x = h0; vh0.y = h1; vh1.x = h2; vh1.y = h3;
    vl0.x = l0; vl0.y = l1; vl1.x = l2; vl1.y = l3;
    ((__nv_bfloat162*)g_hhi)[2 * i4] = vh0;
    ((__nv_bfloat162*)g_hhi)[2 * i4 + 1] = vh1;
    ((__nv_bfloat162*)g_hlo)[2 * i4] = vl0;
    ((__nv_bfloat162*)g_hlo)[2 * i4 + 1] = vl1;
}

// ---------------- unified bf16-split HMMA GEMM (BN=128) ----------------
// EPI=0: fp32 C (z also offsets A/B by sAz/sBz elements along k).
// EPI=2: fused head (a1 compute + scores + reductions).
template <int EPI>
__global__ void __launch_bounds__(256, 2) gemm_bs(
    const __nv_bfloat16* __restrict__ Ahi, const __nv_bfloat16* __restrict__ Alo,
    int lda, long sAz,
    const __nv_bfloat16* __restrict__ Bhi, const __nv_bfloat16* __restrict__ Blo,
    int ldb, long sBz,
    float* __restrict__ C, __nv_bfloat16* __restrict__ Chi,
    __nv_bfloat16* __restrict__ Clo,
    const float* __restrict__ bias, int ldc, long sCz, int K,
    const float* __restrict__ b2, const float* __restrict__ W3,
    const float* __restrict__ b3,
    const float* __restrict__ hwhp, const float* __restrict__ zv,
    const int* __restrict__ permp, const float* __restrict__ Wzp,
    const float* __restrict__ b1p)
{
    extern __shared__ char sm[];
    __shared__ float red[128][5];
    __shared__ float wr[8];
    __shared__ float s_wz[HDIM], s_b1[HDIM];
    const uint32_t sb = smem_u32(sm);
    const int tid = threadIdx.x;
    const int lane = tid & 31;
    const int wid = tid >> 5;
    const int warpM = wid >> 2;
    const int warpN = wid & 3;

    const int nBase = blockIdx.x * 128;
    const int mBase = blockIdx.y * BM;
    const __nv_bfloat16* ahiz = Ahi + (size_t)blockIdx.z * sAz;
    const __nv_bfloat16* aloz = Alo + (size_t)blockIdx.z * sAz;
    const __nv_bfloat16* bhi = Bhi + (size_t)blockIdx.z * sBz;
    const __nv_bfloat16* blo = Blo + (size_t)blockIdx.z * sBz;

    if (EPI == 2) {
        if (tid < HDIM) {
            s_wz[tid] = Wzp[(size_t)blockIdx.z * HDIM + tid];
            s_b1[tid] = b1p[(size_t)blockIdx.z * HDIM + tid];
        }
        __syncthreads();
    }

    const uint32_t laneOff =
        (uint32_t)(((lane & 7) + ((lane >> 3) & 1) * 8) * ROWB + (lane >> 4) * 16);
    const int NIT = K / BK;

    float acc[4][4][4];
#pragma unroll
    for (int i = 0; i < 4; i++)
#pragma unroll
        for (int j = 0; j < 4; j++)
#pragma unroll
            for (int k = 0; k < 4; k++) acc[i][j][k] = 0.f;

#define A_COMPUTE(stage, k0)                                                   \
    do {                                                                       \
        uint32_t stoff = (uint32_t)(stage) * STG_BYTES;                        \
        const float* hwh_d = hwhp + (size_t)blockIdx.z * BB * HDIM;            \
        _Pragma("unroll")                                                      \
        for (int t = 0; t < 2; t++) {                                          \
            int u = tid + t * 256;                                             \
            int r = u >> 2, ch = u & 3;                                        \
            int gm = mBase + r;                                                \
            int b = (gm < BB) ? gm : gm - BB;                                  \
            int src = (gm < BB) ? b : __ldg(permp + b);                        \
            float zb = __ldg(zv + (size_t)b * DDIM + blockIdx.z);              \
            const float* hr = hwh_d + (size_t)src * HDIM + (k0) + ch * 8;      \
            float4 v0 = __ldg((const float4*)hr);                              \
            float4 v1 = __ldg((const float4*)(hr + 4));                        \
            float hv[8] = {v0.x, v0.y, v0.z, v0.w, v1.x, v1.y, v1.z, v1.w};    \
            uint32_t hp[4], lp[4];                                             \
            _Pragma("unroll")                                                  \
            for (int j = 0; j < 4; j++) {                                      \
                int kk = (k0) + ch * 8 + 2 * j;                                \
                float a0 = eluf(hv[2*j]   + fmaf(zb, s_wz[kk],   s_b1[kk]));   \
                float a1v = eluf(hv[2*j+1] + fmaf(zb, s_wz[kk+1], s_b1[kk+1]));\
                __nv_bfloat16 hh0, ll0, hh1, ll1;                              \
                hilo(a0, hh0, ll0); hilo(a1v, hh1, ll1);                       \
                __nv_bfloat162 ph; ph.x = hh0; ph.y = hh1;                     \
                __nv_bfloat162 pl; pl.x = ll0; pl.y = ll1;                     \
                hp[j] = *(uint32_t*)&ph; lp[j] = *(uint32_t*)&pl;              \
            }                                                                  \
            uint32_t so = (uint32_t)(r * ROWB + ch * 16);                      \
            *(uint4*)(sm + stoff + 0 * MAT_BYTES + so) =                       \
                make_uint4(hp[0], hp[1], hp[2], hp[3]);                        \
            *(uint4*)(sm + stoff + 1 * MAT_BYTES + so) =                       \
                make_uint4(lp[0], lp[1], lp[2], lp[3]);                        \
        }                                                                      \
    } while (0)

#define BS_LOAD(stage, k0)                                                     \
    do {                                                                       \
        uint32_t st = sb + (uint32_t)(stage)*STG_BYTES;                        \
        if (EPI == 2) {                                                        \
            A_COMPUTE(stage, k0);                                              \
        } else {                                                               \
            _Pragma("unroll")                                                  \
            for (int t = 0; t < 2; t++) {                                      \
                int ci = tid + t * 256;                                        \
                int r = ci >> 2, ch = ci & 3;                                  \
                uint32_t so = (uint32_t)(r * ROWB + ch * 16);                  \
                size_t goA = (size_t)(mBase + r) * lda + (k0) + ch * 8;        \
                CP16(st + 0 * MAT_BYTES + so, ahiz + goA);                     \
                CP16(st + 1 * MAT_BYTES + so, aloz + goA);                     \
            }                                                                  \
        }                                                                      \
        _Pragma("unroll")                                                      \
        for (int t = 0; t < 2; t++) {                                          \
            int ci = tid + t * 256;                                            \
            int r = ci >> 2, ch = ci & 3;                                      \
            uint32_t so = (uint32_t)(r * ROWB + ch * 16);                      \
            size_t goB = (size_t)(nBase + r) * ldb + (k0) + ch * 8;            \
            CP16(st + 2 * MAT_BYTES + so, bhi + goB);                          \
            CP16(st + 3 * MAT_BYTES + so, blo + goB);                          \
        }                                                                      \
    } while (0)

    BS_LOAD(0, 0);
    CP_COMMIT();

#pragma unroll 1
    for (int it = 0; it < NIT; it++) {
        if (it + 1 < NIT) {
            BS_LOAD((it + 1) & 1, (it + 1) * BK);
            CP_COMMIT();
            CP_WAIT1();
        } else {
            CP_WAIT0();
        }
        __syncthreads();

        uint32_t st = sb + (uint32_t)(it & 1) * STG_BYTES;
        uint32_t aH = st + 0 * MAT_BYTES + (uint32_t)(warpM * 64) * ROWB + laneOff;
        uint32_t aL = st + 1 * MAT_BYTES + (uint32_t)(warpM * 64) * ROWB + laneOff;
        uint32_t bH = st + 2 * MAT_BYTES + (uint32_t)(warpN * 32) * ROWB + laneOff;
        uint32_t bL = st + 3 * MAT_BYTES + (uint32_t)(warpN * 32) * ROWB + laneOff;

#pragma unroll
        for (int ks = 0; ks < 2; ks++) {
            const uint32_t kb = ks * 32;
            uint32_t ah[4][4], al[4][4], bh[2][4], bl[2][4];
#pragma unroll
            for (int mt = 0; mt < 4; mt++) {
                ldmx4(ah[mt], aH + (uint32_t)(mt * 16) * ROWB + kb);
                ldmx4(al[mt], aL + (uint32_t)(mt * 16) * ROWB + kb);
            }
#pragma unroll
            for (int p = 0; p < 2; p++) {
                ldmx4(bh[p], bH + (uint32_t)(p * 16) * ROWB + kb);
                ldmx4(bl[p], bL + (uint32_t)(p * 16) * ROWB + kb);
            }
#pragma unroll
            for (int mt = 0; mt < 4; mt++) {
#pragma unroll
                for (int nt = 0; nt < 4; nt++) {
                    const int p = nt >> 1, q = nt & 1;
                    mma16816(acc[mt][nt], ah[mt], bh[p][q], bh[p][q + 2]);
                    mma16816(acc[mt][nt], ah[mt], bl[p][q], bl[p][q + 2]);
                    mma16816(acc[mt][nt], al[mt], bh[p][q], bh[p][q + 2]);
                }
            }
        }
        __syncthreads();
    }
#undef BS_LOAD
#undef A_COMPUTE

    if (EPI == 2) {
        const float* b2z = b2 + (size_t)blockIdx.z * HDIM;
        const float* w3z = W3 + (size_t)blockIdx.z * HDIM;
        const float b3d = b3[blockIdx.z];
        const bool joint = (blockIdx.y < 4);
#pragma unroll
        for (int mt = 0; mt < 4; mt++) {
            float s0 = 0.f, s1 = 0.f;
#pragma unroll
            for (int nt = 0; nt < 4; nt++) {
                int n0 = warpN * 32 + nt * 8 + (lane & 3) * 2;
                float w0 = __ldg(w3z + n0), w1 = __ldg(w3z + n0 + 1);
                float c0 = __ldg(b2z + n0), c1 = __ldg(b2z + n0 + 1);
                s0 += eluf(acc[mt][nt][0] + c0) * w0 + eluf(acc[mt][nt][1] + c1) * w1;
                s1 += eluf(acc[mt][nt][2] + c0) * w0 + eluf(acc[mt][nt][3] + c1) * w1;
            }
            s0 += __shfl_xor_sync(0xffffffffu, s0, 1);
            s0 += __shfl_xor_sync(0xffffffffu, s0, 2);
            s1 += __shfl_xor_sync(0xffffffffu, s1, 1);
            s1 += __shfl_xor_sync(0xffffffffu, s1, 2);
            if ((lane & 3) == 0) {
                int r0 = warpM * 64 + mt * 16 + (lane >> 2);
                red[r0][warpN] = s0;
                red[r0 + 8][warpN] = s1;
            }
        }
        __syncthreads();
        float val = 0.f;
        if (tid < 128) {
            float s = red[tid][0] + red[tid][1] + red[tid][2] + red[tid][3] + b3d;
            val = joint ? s : expf(s);
        }
#pragma unroll
        for (int off = 16; off; off >>= 1)
            val += __shfl_xor_sync(0xffffffffu, val, off);
        if (lane == 0) wr[wid] = val;
        __syncthreads();
        if (tid == 0) {
            float s = wr[0] + wr[1] + wr[2] + wr[3];
            int slot = blockIdx.z * 8 + blockIdx.y;
            if (joint) { g_js[slot] = s; g_es[slot] = 0.f; }
            else       { g_js[slot] = 0.f; g_es[slot] = s; }
        }
        return;
    }

#pragma unroll
    for (int mt = 0; mt < 4; mt++) {
        int m0 = mBase + warpM * 64 + mt * 16 + (lane >> 2);
#pragma unroll
        for (int nt = 0; nt < 4; nt++) {
            int n0 = nBase + warpN * 32 + nt * 8 + (lane & 3) * 2;
            float* Cz = C + (size_t)blockIdx.z * sCz;
            *(float2*)(Cz + (size_t)m0 * ldc + n0) =
                make_float2(acc[mt][nt][0], acc[mt][nt][1]);
            *(float2*)(Cz + (size_t)(m0 + 8) * ldc + n0) =
                make_float2(acc[mt][nt][2], acc[mt][nt][3]);
        }
    }
}

__global__ void finalize_kernel(float* __restrict__ out)
{
    int t = threadIdx.x;
    float acc = 0.f;
    for (int d = t; d < DDIM; d += 32) {
        float js = 0.f, es = 0.f;
#pragma unroll
        for (int c = 0; c < 8; c++) { js += g_js[d * 8 + c]; es += g_es[d * 8 + c]; }
        acc += js * (1.f / BB) - logf(es * (1.f / BB));
    }
#pragma unroll
    for (int off = 16; off; off >>= 1)
        acc += __shfl_xor_sync(0xffffffffu, acc, off);
    if (t == 0) out[0] = -acc * (1.f / DDIM);
}

// ---------------------------------------------------------------------------
extern "C" void kernel_launch(void* const* d_in, const int* in_sizes, int n_in,
                              void* d_out, int out_size)
{
    const float* x   = (const float*)d_in[0];
    const float* z   = (const float*)d_in[1];
    const int*   perm= (const int*)  d_in[2];
    const float* Wg1 = (const float*)d_in[3];
    const float* bg1 = (const float*)d_in[4];
    const float* Wg2 = (const float*)d_in[5];
    const float* bg2 = (const float*)d_in[6];
    const float* Wh  = (const float*)d_in[7];
    const float* Wz  = (const float*)d_in[8];
    const float* b1  = (const float*)d_in[9];
    const float* W2  = (const float*)d_in[10];
    const float* b2  = (const float*)d_in[11];
    const float* W3  = (const float*)d_in[12];
    const float* b3  = (const float*)d_in[13];

    __nv_bfloat16 *h1hi, *h1lo, *wg2thi, *wg2tlo, *hhi, *hlo, *whthi, *whtlo;
    __nv_bfloat16 *w2thi, *w2tlo;
    float *hwh, *part;
    cudaGetSymbolAddress((void**)&h1hi,   g_h1hi);
    cudaGetSymbolAddress((void**)&h1lo,   g_h1lo);
    cudaGetSymbolAddress((void**)&wg2thi, g_wg2thi);
    cudaGetSymbolAddress((void**)&wg2tlo, g_wg2tlo);
    cudaGetSymbolAddress((void**)&hhi,    g_hhi);
    cudaGetSymbolAddress((void**)&hlo,    g_hlo);
    cudaGetSymbolAddress((void**)&whthi,  g_whthi);
    cudaGetSymbolAddress((void**)&whtlo,  g_whtlo);
    cudaGetSymbolAddress((void**)&w2thi,  g_w2thi);
    cudaGetSymbolAddress((void**)&w2tlo,  g_w2tlo);
    cudaGetSymbolAddress((void**)&hwh,    g_hWh);
    cudaGetSymbolAddress((void**)&part,   g_part);

    // merged weight conversion (single launch)
    transconv_all_kernel<<<CT_ALL, 256>>>(Wg2, Wh, W2);

    // K1: fused fp32->hi/lo loader + bf16-split HMMA (R9 exact)
    cudaFuncSetAttribute(gemm_k1_kernel,
                         cudaFuncAttributeMaxDynamicSharedMemorySize, K1_SMEM);
    gemm_k1_kernel<<<dim3(G1D / K1_BN, BB / BM, K1_KS), 256, K1_SMEM>>>(x, Wg1);
    reduce_h1_kernel<<<(BB * G1D) / 4 / 256, 256>>>(bg1);

    cudaFuncSetAttribute(gemm_bs<0>,
                         cudaFuncAttributeMaxDynamicSharedMemorySize, GEMM_SMEM);
    cudaFuncSetAttribute(gemm_bs<2>,
                         cudaFuncAttributeMaxDynamicSharedMemorySize, GEMM_SMEM);

    // K2 (k-split x4): partials = h1 @ Wg2  (fp32), then reduce+elu -> bf16
    gemm_bs<0><<<dim3(PDIM / 128, BB / BM, K2_KS), 256, GEMM_SMEM>>>(
        h1hi, h1lo, G1D, (long)K2_KCHUNK, wg2thi, wg2tlo, G1D, (long)K2_KCHUNK,
        part, nullptr, nullptr, nullptr, PDIM, (long)BB * PDIM, K2_KCHUNK,
        nullptr, nullptr, nullptr, nullptr, nullptr, nullptr, nullptr, nullptr);
    reduce_h2_kernel<<<(BB * PDIM) / 4 / 256, 256>>>(bg2);

    // K3: hWh[d] = h @ WhT[d]  (fp32)
    gemm_bs<0><<<dim3(1, BB / BM, DDIM), 256, GEMM_SMEM>>>(
        hhi, hlo, PDIM, 0, whthi, whtlo, PDIM, (long)HDIM * PDIM,
        hwh, nullptr, nullptr, nullptr, HDIM, (long)BB * HDIM, PDIM,
        nullptr, nullptr, nullptr, nullptr, nullptr, nullptr, nullptr, nullptr);

    // head: fused a1 compute + a2 GEMM + scores + reductions
    gemm_bs<2><<<dim3(1, (2 * BB) / BM, DDIM), 256, GEMM_SMEM>>>(
        nullptr, nullptr, HDIM, 0,
        w2thi, w2tlo, HDIM, (long)HDIM * HDIM,
        nullptr, nullptr, nullptr, nullptr, HDIM, 0, HDIM,
        b2, W3, b3, hwh, z, perm, Wz, b1);

    finalize_kernel<<<1, 32>>>((float*)d_out);
}